// round 12
// baseline (speedup 1.0000x reference)
#include <cuda_runtime.h>
#include <math.h>

#define BNH 32
#define LL  1024
#define DD  64
#define RR  129
#define AVG 192      // g_av stride (cols 129..191 zero)
#define QEG 136      // g_qe stride
#define QESTR 132    // qe smem stride

__device__ float g_av[(size_t)BNH * LL * AVG];        // 25 MB
__device__ float g_qe[(size_t)BNH * LL * QEG];        // 17.8 MB
__device__ float g_scores[(size_t)BNH * LL * LL];     // 128 MB raw scores (+ p scratch if gp null)

#define FIX_SCALE 4503599627370496.0f   /* 2^52 */
#define FIX_INV   (1.0f / 4503599627370496.0f)

__device__ __forceinline__ unsigned tf32b(float x) {
    unsigned u;
    asm("cvt.rna.tf32.f32 %0, %1;" : "=r"(u) : "f"(x));
    return u;
}
__device__ __forceinline__ float tf32r(float x) { return __uint_as_float(tf32b(x)); }
__device__ __forceinline__ float4 tf32r4(float4 a) {
    a.x = tf32r(a.x); a.y = tf32r(a.y); a.z = tf32r(a.z); a.w = tf32r(a.w);
    return a;
}

#define MMA_TF32(c0,c1,c2,c3,a0,a1,a2,a3,b0,b1)                               \
    asm volatile("mma.sync.aligned.m16n8k8.row.col.f32.tf32.tf32.f32 "        \
                 "{%0,%1,%2,%3}, {%4,%5,%6,%7}, {%8,%9}, {%0,%1,%2,%3};"      \
                 : "+f"(c0), "+f"(c1), "+f"(c2), "+f"(c3)                      \
                 : "r"(a0), "r"(a1), "r"(a2), "r"(a3), "r"(b0), "r"(b1))

// ===================== K_qe: g_qe = q . emb_k^T =====================
#define QE_SMEM ((4352 + 9248) * 4)

extern "C" __global__ void __launch_bounds__(256)
qe_kernel(const float* __restrict__ gq, const float* __restrict__ gek)
{
    extern __shared__ float sm[];
    float* q_s = sm;            // 64 x 68
    float* ek  = sm + 4352;     // 136 x 68 (rows >=129 zero)

    const int b    = blockIdx.y;
    const int i0   = blockIdx.x * 64;
    const int tid  = threadIdx.x;
    const int lane = tid & 31;
    const int warp = tid >> 5;
    const int gid  = lane >> 2;
    const int tid4 = lane & 3;

    {
        const float4* q4 = (const float4*)(gq + ((size_t)b * LL + i0) * DD);
        #pragma unroll
        for (int s = 0; s < 4; s++) {
            int f = tid + s * 256;
            int r = f >> 4, c4 = f & 15;
            *(float4*)(q_s + r * 68 + c4 * 4) = tf32r4(q4[f]);
        }
        for (int e = tid; e < 136 * 64; e += 256) {
            int r = e >> 6, d = e & 63;
            ek[r * 68 + d] = (r < RR) ? tf32r(gek[r * 64 + d]) : 0.f;
        }
    }
    __syncthreads();

    for (int t = warp; t < 68; t += 8) {
        int mt = t / 17, nt = t % 17;
        float c0 = 0.f, c1 = 0.f, c2 = 0.f, c3 = 0.f;
        #pragma unroll
        for (int ks = 0; ks < 8; ks++) {
            const float* qa = q_s + (mt * 16 + gid) * 68 + ks * 8 + tid4;
            unsigned a0 = __float_as_uint(qa[0]);
            unsigned a1 = __float_as_uint(qa[8 * 68]);
            unsigned a2 = __float_as_uint(qa[4]);
            unsigned a3 = __float_as_uint(qa[8 * 68 + 4]);
            const float* kb = ek + (nt * 8 + gid) * 68 + ks * 8 + tid4;
            unsigned b0 = __float_as_uint(kb[0]);
            unsigned b1 = __float_as_uint(kb[4]);
            MMA_TF32(c0, c1, c2, c3, a0, a1, a2, a3, b0, b1);
        }
        int col = nt * 8 + tid4 * 2;
        float* o_lo = g_qe + ((size_t)b * LL + i0 + mt * 16 + gid) * QEG + col;
        *(float2*)o_lo            = make_float2(c0, c1);
        *(float2*)(o_lo + 8*QEG)  = make_float2(c2, c3);
    }
}

// ============ K_score+softmax: scores -> softmax -> p + av ============
// smem: q_s[64*68]@0, k_s[64*68]@4352 (-> a64 after GEMM), qe_s[64*132]@8704,
//       posa[1024]@17152  => 18176 floats = 72704 B  (3 CTAs/SM)
#define SC_SMEM (18176 * 4)

extern "C" __global__ void __launch_bounds__(256, 3)
score_softmax_kernel(const float* __restrict__ gq, const float* __restrict__ gk,
                     const float* __restrict__ gw, const int* __restrict__ gpos,
                     const unsigned char* __restrict__ gmask, float* __restrict__ gp)
{
    extern __shared__ float sm[];
    float* q_s  = sm;
    float* k_s  = sm + 4352;
    float* qe_s = sm + 8704;
    int*   posa = (int*)(sm + 17152);

    const int b    = blockIdx.y;
    const int i0   = blockIdx.x * 64;
    const int tid  = threadIdx.x;
    const int lane = tid & 31;
    const int warp = tid >> 5;          // 0..7
    const unsigned FULL = 0xffffffffu;
    const int gid  = lane >> 2;
    const int tid4 = lane & 3;
    const int mrow = (warp & 3) * 16;
    const int ncol = (warp >> 2) * 32;

    float* pdst = gp ? gp : g_scores;

    // ---------------- loads ----------------
    {
        const float4* q4 = (const float4*)(gq + ((size_t)b * LL + i0) * DD);
        #pragma unroll
        for (int s = 0; s < 4; s++) {
            int f = tid + s * 256;
            int r = f >> 4, c4 = f & 15;
            *(float4*)(q_s + r * 68 + c4 * 4) = tf32r4(q4[f]);
        }
        #pragma unroll
        for (int t = tid; t < LL; t += 256) posa[t] = gpos[b * LL + t];
        for (int idx = tid; idx < 64 * 33; idx += 256) {
            int r = idx / 33, c4 = idx % 33;
            *(float4*)(qe_s + r * QESTR + c4 * 4) =
                *(const float4*)(g_qe + ((size_t)b * LL + i0 + r) * QEG + c4 * 4);
        }
    }
    __syncthreads();

    // persistent A-fragments of q (already tf32-rounded in smem)
    unsigned af[8][4];
    #pragma unroll
    for (int ks = 0; ks < 8; ks++) {
        const float* qa = q_s + (mrow + gid) * 68 + ks * 8 + tid4;
        af[ks][0] = __float_as_uint(qa[0]);
        af[ks][1] = __float_as_uint(qa[8 * 68]);
        af[ks][2] = __float_as_uint(qa[4]);
        af[ks][3] = __float_as_uint(qa[8 * 68 + 4]);
    }

    const int pil = posa[i0 + mrow + gid];
    const int pih = posa[i0 + mrow + gid + 8];
    const size_t row_lo = ((size_t)b * LL + i0 + mrow + gid) * LL;
    const size_t row_hi = row_lo + 8 * LL;

    // ---------------- GEMM phase: 16 k-tiles of 64 j ----------------
    for (int jt = 0; jt < 16; jt++) {
        {
            const float4* k4 = (const float4*)(gk + ((size_t)b * LL + jt * 64) * DD);
            #pragma unroll
            for (int s = 0; s < 4; s++) {
                int f = tid + s * 256;
                int r = f >> 4, c4 = f & 15;
                *(float4*)(k_s + r * 68 + c4 * 4) = tf32r4(k4[f]);
            }
        }
        __syncthreads();

        float acc[4][4];
        #pragma unroll
        for (int nt = 0; nt < 4; nt++)
            #pragma unroll
            for (int x = 0; x < 4; x++) acc[nt][x] = 0.f;

        #pragma unroll
        for (int ks = 0; ks < 8; ks++)
            #pragma unroll
            for (int nt = 0; nt < 4; nt++) {
                const float* kb = k_s + (ncol + nt * 8 + gid) * 68 + ks * 8 + tid4;
                unsigned b0 = __float_as_uint(kb[0]);
                unsigned b1 = __float_as_uint(kb[4]);
                MMA_TF32(acc[nt][0], acc[nt][1], acc[nt][2], acc[nt][3],
                         af[ks][0], af[ks][1], af[ks][2], af[ks][3], b0, b1);
            }

        #pragma unroll
        for (int nt = 0; nt < 4; nt++) {
            int jg = jt * 64 + ncol + nt * 8 + tid4 * 2;
            float2 wl = *(const float2*)(gw + row_lo + jg);
            float2 wh = *(const float2*)(gw + row_hi + jg);
            uchar2 ml = *(const uchar2*)(gmask + row_lo + jg);
            uchar2 mh = *(const uchar2*)(gmask + row_hi + jg);
            int pj0 = posa[jg], pj1 = posa[jg + 1];
            int d00 = max(-64, min(64, pj0 - pil)) + 64;
            int d01 = max(-64, min(64, pj1 - pil)) + 64;
            int d10 = max(-64, min(64, pj0 - pih)) + 64;
            int d11 = max(-64, min(64, pj1 - pih)) + 64;
            float s00 = (acc[nt][0] + qe_s[(mrow + gid)     * QESTR + d00] + wl.x) * 0.125f;
            float s01 = (acc[nt][1] + qe_s[(mrow + gid)     * QESTR + d01] + wl.y) * 0.125f;
            float s10 = (acc[nt][2] + qe_s[(mrow + gid + 8) * QESTR + d10] + wh.x) * 0.125f;
            float s11 = (acc[nt][3] + qe_s[(mrow + gid + 8) * QESTR + d11] + wh.y) * 0.125f;
            if (ml.x) s00 = -INFINITY;
            if (ml.y) s01 = -INFINITY;
            if (mh.x) s10 = -INFINITY;
            if (mh.y) s11 = -INFINITY;
            *(float2*)(g_scores + row_lo + jg) = make_float2(s00, s01);
            *(float2*)(g_scores + row_hi + jg) = make_float2(s10, s11);
        }
        __syncthreads();
    }

    // ---------------- softmax phase: 8 rows per warp (scores hit L2) ----------------
    unsigned long long* a64 = (unsigned long long*)k_s + (size_t)warp * 264;
    for (int rr = 0; rr < 8; rr++) {
        const int i = warp * 8 + rr;
        const size_t grow = ((size_t)b * LL + i0 + i) * LL;
        const float4* s4 = (const float4*)(g_scores + grow);
        float4 r4[8];
        #pragma unroll
        for (int c = 0; c < 8; c++) r4[c] = s4[lane + 32 * c];

        float m = -INFINITY;
        #pragma unroll
        for (int c = 0; c < 8; c++) {
            m = fmaxf(m, fmaxf(fmaxf(r4[c].x, r4[c].y), fmaxf(r4[c].z, r4[c].w)));
        }
        #pragma unroll
        for (int o = 16; o > 0; o >>= 1) m = fmaxf(m, __shfl_xor_sync(FULL, m, o));

        float sum = 0.f;
        #pragma unroll
        for (int c = 0; c < 8; c++) {
            r4[c].x = __expf(r4[c].x - m); sum += r4[c].x;
            r4[c].y = __expf(r4[c].y - m); sum += r4[c].y;
            r4[c].z = __expf(r4[c].z - m); sum += r4[c].z;
            r4[c].w = __expf(r4[c].w - m); sum += r4[c].w;
        }
        #pragma unroll
        for (int o = 16; o > 0; o >>= 1) sum += __shfl_xor_sync(FULL, sum, o);
        float inv = 1.0f / sum;

        #pragma unroll
        for (int c = 0; c < 9; c++) {
            int idx = lane + 32 * c;
            if (idx < 264) a64[idx] = 0ull;
        }
        __syncwarp();

        const int pi = posa[i0 + i];
        const int bank = lane & 1;
        float4* p4 = (float4*)(pdst + grow);
        #pragma unroll
        for (int c = 0; c < 8; c++) {
            float4 pv;
            pv.x = r4[c].x * inv; pv.y = r4[c].y * inv;
            pv.z = r4[c].z * inv; pv.w = r4[c].w * inv;
            p4[lane + 32 * c] = pv;
            int j0 = (lane + 32 * c) * 4;
            int df0 = max(-64, min(64, posa[j0    ] - pi)) + 64;
            int df1 = max(-64, min(64, posa[j0 + 1] - pi)) + 64;
            int df2 = max(-64, min(64, posa[j0 + 2] - pi)) + 64;
            int df3 = max(-64, min(64, posa[j0 + 3] - pi)) + 64;
            atomicAdd(a64 + df0 * 2 + bank, (unsigned long long)(pv.x * FIX_SCALE));
            atomicAdd(a64 + df1 * 2 + bank, (unsigned long long)(pv.y * FIX_SCALE));
            atomicAdd(a64 + df2 * 2 + bank, (unsigned long long)(pv.z * FIX_SCALE));
            atomicAdd(a64 + df3 * 2 + bank, (unsigned long long)(pv.w * FIX_SCALE));
        }
        __syncwarp();

        float* avout = g_av + ((size_t)b * LL + i0 + i) * AVG;
        #pragma unroll
        for (int c = 0; c < 6; c++) {
            int idx = lane + 32 * c;
            float val = 0.f;
            if (idx < RR)
                val = __ull2float_rn(a64[idx * 2] + a64[idx * 2 + 1]) * FIX_INV;
            avout[idx] = val;
        }
        __syncwarp();
    }
}

// ===================== K_pv: out = p @ v + av @ emb_v =====================
#define NT2 256

extern "C" __global__ void __launch_bounds__(NT2, 4)
pv_kernel(const float* __restrict__ gp_in, const float* __restrict__ gv,
          const float* __restrict__ gev, float* __restrict__ gout)
{
    __shared__ float ps2[64 * 68];
    __shared__ float vs2[64 * 72];

    const int b    = blockIdx.y;
    const int i0b  = blockIdx.x * 64;
    const int tid  = threadIdx.x;
    const int lane = tid & 31;
    const int warp = tid >> 5;
    const int gid  = lane >> 2;
    const int tid4 = lane & 3;
    const int mrow = (warp & 3) * 16;
    const int ncol = (warp >> 2) * 32;

    const float* psrc = gp_in ? gp_in : g_scores;

    float acc[4][4];
    #pragma unroll
    for (int nt = 0; nt < 4; nt++)
        #pragma unroll
        for (int x = 0; x < 4; x++) acc[nt][x] = 0.f;

    for (int t = 0; t < 19; t++) {
        if (t < 16) {
            const float4* pa = (const float4*)(psrc + ((size_t)b * LL + i0b) * LL + t * 64);
            const float4* va = (const float4*)(gv + ((size_t)b * LL + t * 64) * DD);
            #pragma unroll
            for (int s = 0; s < 4; s++) {
                int f = tid + s * NT2;
                int r = f >> 4, c4 = f & 15;
                *(float4*)(ps2 + r * 68 + c4 * 4) = tf32r4(pa[r * 256 + c4]);
                *(float4*)(vs2 + r * 72 + c4 * 4) = tf32r4(va[f]);
            }
        } else {
            int kc = t - 16;
            const float4* aa = (const float4*)(g_av + ((size_t)b * LL + i0b) * AVG + kc * 64);
            #pragma unroll
            for (int s = 0; s < 4; s++) {
                int f = tid + s * NT2;
                int r = f >> 4, c4 = f & 15;
                *(float4*)(ps2 + r * 68 + c4 * 4) = tf32r4(aa[r * (AVG/4) + c4]);
                int kr = kc * 64 + r;
                float4 ev = make_float4(0.f, 0.f, 0.f, 0.f);
                if (kr < RR)
                    ev = tf32r4(((const float4*)(gev + kr * DD))[c4]);
                *(float4*)(vs2 + r * 72 + c4 * 4) = ev;
            }
        }
        __syncthreads();

        #pragma unroll
        for (int ks = 0; ks < 8; ks++) {
            unsigned a0 = __float_as_uint(ps2[(mrow + gid)     * 68 + ks * 8 + tid4    ]);
            unsigned a1 = __float_as_uint(ps2[(mrow + gid + 8) * 68 + ks * 8 + tid4    ]);
            unsigned a2 = __float_as_uint(ps2[(mrow + gid)     * 68 + ks * 8 + tid4 + 4]);
            unsigned a3 = __float_as_uint(ps2[(mrow + gid + 8) * 68 + ks * 8 + tid4 + 4]);
            #pragma unroll
            for (int nt = 0; nt < 4; nt++) {
                unsigned b0 = __float_as_uint(vs2[(ks * 8 + tid4)     * 72 + ncol + nt * 8 + gid]);
                unsigned b1 = __float_as_uint(vs2[(ks * 8 + tid4 + 4) * 72 + ncol + nt * 8 + gid]);
                MMA_TF32(acc[nt][0], acc[nt][1], acc[nt][2], acc[nt][3],
                         a0, a1, a2, a3, b0, b1);
            }
        }
        __syncthreads();
    }

    #pragma unroll
    for (int nt = 0; nt < 4; nt++) {
        int col = ncol + nt * 8 + tid4 * 2;
        *(float2*)(gout + ((size_t)b * LL + i0b + mrow + gid)     * DD + col) =
            make_float2(acc[nt][0], acc[nt][1]);
        *(float2*)(gout + ((size_t)b * LL + i0b + mrow + gid + 8) * DD + col) =
            make_float2(acc[nt][2], acc[nt][3]);
    }
}

extern "C" void kernel_launch(void* const* d_in, const int* in_sizes, int n_in,
                              void* d_out, int out_size)
{
    const float* q   = (const float*)d_in[0];
    const float* k   = (const float*)d_in[1];
    const float* v   = (const float*)d_in[2];
    const float* w   = (const float*)d_in[3];
    const float* ek  = (const float*)d_in[4];
    const float* ev  = (const float*)d_in[5];
    const int*   pos = (const int*)d_in[6];
    const unsigned char* mask = (const unsigned char*)d_in[7];

    const long OUT_N = (long)BNH * LL * DD;   // 2,097,152
    const long P_N   = (long)BNH * LL * LL;   // 33,554,432

    float* outp = nullptr;
    float* pp   = nullptr;
    if ((long)out_size == OUT_N) {
        outp = (float*)d_out;
    } else if ((long)out_size == P_N) {
        pp = (float*)d_out;
    } else {
        outp = (float*)d_out;
        pp   = (float*)d_out + OUT_N;
    }

    cudaFuncSetAttribute(qe_kernel,
                         cudaFuncAttributeMaxDynamicSharedMemorySize, QE_SMEM);
    cudaFuncSetAttribute(score_softmax_kernel,
                         cudaFuncAttributeMaxDynamicSharedMemorySize, SC_SMEM);

    dim3 grid(LL / 64, BNH);                  // (16, 32)
    qe_kernel<<<grid, 256, QE_SMEM>>>(q, ek);
    score_softmax_kernel<<<grid, 256, SC_SMEM>>>(q, k, w, pos, mask, pp);
    if (outp)
        pv_kernel<<<grid, NT2>>>(pp, v, ev, outp);
}

// round 13
// speedup vs baseline: 1.4638x; 1.4638x over previous
#include <cuda_runtime.h>
#include <math.h>

#define BNH 32
#define LL  1024
#define DD  64
#define RR  129
#define AVG 192      // g_av stride (cols 129..191 zero)
#define QEG 136      // g_qe stride
#define QESTR 132    // qe smem stride

__device__ float g_av[(size_t)BNH * LL * AVG];        // 25 MB
__device__ float g_qe[(size_t)BNH * LL * QEG];        // 17.8 MB
__device__ float g_scores[(size_t)BNH * LL * LL];     // 128 MB raw scores (+ p scratch if gp null)

#define FIX_SCALE 4503599627370496.0f   /* 2^52 */
#define FIX_INV   (1.0f / 4503599627370496.0f)

__device__ __forceinline__ unsigned tf32b(float x) {
    unsigned u;
    asm("cvt.rna.tf32.f32 %0, %1;" : "=r"(u) : "f"(x));
    return u;
}
__device__ __forceinline__ float tf32r(float x) { return __uint_as_float(tf32b(x)); }
__device__ __forceinline__ float4 tf32r4(float4 a) {
    a.x = tf32r(a.x); a.y = tf32r(a.y); a.z = tf32r(a.z); a.w = tf32r(a.w);
    return a;
}

#define MMA_TF32(c0,c1,c2,c3,a0,a1,a2,a3,b0,b1)                               \
    asm volatile("mma.sync.aligned.m16n8k8.row.col.f32.tf32.tf32.f32 "        \
                 "{%0,%1,%2,%3}, {%4,%5,%6,%7}, {%8,%9}, {%0,%1,%2,%3};"      \
                 : "+f"(c0), "+f"(c1), "+f"(c2), "+f"(c3)                      \
                 : "r"(a0), "r"(a1), "r"(a2), "r"(a3), "r"(b0), "r"(b1))

// ===================== K_qe: g_qe = q . emb_k^T =====================
#define QE_SMEM ((4352 + 9248) * 4)

extern "C" __global__ void __launch_bounds__(256)
qe_kernel(const float* __restrict__ gq, const float* __restrict__ gek)
{
    extern __shared__ float sm[];
    float* q_s = sm;            // 64 x 68
    float* ek  = sm + 4352;     // 136 x 68 (rows >=129 zero)

    const int b    = blockIdx.y;
    const int i0   = blockIdx.x * 64;
    const int tid  = threadIdx.x;
    const int lane = tid & 31;
    const int warp = tid >> 5;
    const int gid  = lane >> 2;
    const int tid4 = lane & 3;

    {
        const float4* q4 = (const float4*)(gq + ((size_t)b * LL + i0) * DD);
        #pragma unroll
        for (int s = 0; s < 4; s++) {
            int f = tid + s * 256;
            int r = f >> 4, c4 = f & 15;
            *(float4*)(q_s + r * 68 + c4 * 4) = tf32r4(q4[f]);
        }
        for (int e = tid; e < 136 * 64; e += 256) {
            int r = e >> 6, d = e & 63;
            ek[r * 68 + d] = (r < RR) ? tf32r(gek[r * 64 + d]) : 0.f;
        }
    }
    __syncthreads();

    for (int t = warp; t < 68; t += 8) {
        int mt = t / 17, nt = t % 17;
        float c0 = 0.f, c1 = 0.f, c2 = 0.f, c3 = 0.f;
        #pragma unroll
        for (int ks = 0; ks < 8; ks++) {
            const float* qa = q_s + (mt * 16 + gid) * 68 + ks * 8 + tid4;
            unsigned a0 = __float_as_uint(qa[0]);
            unsigned a1 = __float_as_uint(qa[8 * 68]);
            unsigned a2 = __float_as_uint(qa[4]);
            unsigned a3 = __float_as_uint(qa[8 * 68 + 4]);
            const float* kb = ek + (nt * 8 + gid) * 68 + ks * 8 + tid4;
            unsigned b0 = __float_as_uint(kb[0]);
            unsigned b1 = __float_as_uint(kb[4]);
            MMA_TF32(c0, c1, c2, c3, a0, a1, a2, a3, b0, b1);
        }
        int col = nt * 8 + tid4 * 2;
        float* o_lo = g_qe + ((size_t)b * LL + i0 + mt * 16 + gid) * QEG + col;
        *(float2*)o_lo            = make_float2(c0, c1);
        *(float2*)(o_lo + 8*QEG)  = make_float2(c2, c3);
    }
}

// ============ K_score: raw scores = (QK^T + qe[table] + w)/8, mask ============
// smem: q_s[64*68]@0, k_s[64*68]@4352, qe_s[64*132]@8704, posa[1024]@17152
#define SC_SMEM (18176 * 4)

extern "C" __global__ void __launch_bounds__(256, 3)
score_kernel(const float* __restrict__ gq, const float* __restrict__ gk,
             const float* __restrict__ gw, const int* __restrict__ gpos,
             const unsigned char* __restrict__ gmask)
{
    extern __shared__ float sm[];
    float* q_s  = sm;
    float* k_s  = sm + 4352;
    float* qe_s = sm + 8704;
    int*   posa = (int*)(sm + 17152);

    const int b    = blockIdx.y;
    const int i0   = blockIdx.x * 64;
    const int tid  = threadIdx.x;
    const int lane = tid & 31;
    const int warp = tid >> 5;          // 0..7
    const int gid  = lane >> 2;
    const int tid4 = lane & 3;
    const int mrow = (warp & 3) * 16;
    const int ncol = (warp >> 2) * 32;

    // ---------------- loads ----------------
    {
        const float4* q4 = (const float4*)(gq + ((size_t)b * LL + i0) * DD);
        #pragma unroll
        for (int s = 0; s < 4; s++) {
            int f = tid + s * 256;
            int r = f >> 4, c4 = f & 15;
            *(float4*)(q_s + r * 68 + c4 * 4) = tf32r4(q4[f]);
        }
        #pragma unroll
        for (int t = tid; t < LL; t += 256) posa[t] = gpos[b * LL + t];
        for (int idx = tid; idx < 64 * 33; idx += 256) {
            int r = idx / 33, c4 = idx % 33;
            *(float4*)(qe_s + r * QESTR + c4 * 4) =
                *(const float4*)(g_qe + ((size_t)b * LL + i0 + r) * QEG + c4 * 4);
        }
    }
    __syncthreads();

    const int pil = posa[i0 + mrow + gid];
    const int pih = posa[i0 + mrow + gid + 8];
    const size_t row_lo = ((size_t)b * LL + i0 + mrow + gid) * LL;
    const size_t row_hi = row_lo + 8 * LL;

    for (int jt = 0; jt < 16; jt++) {
        {
            const float4* k4 = (const float4*)(gk + ((size_t)b * LL + jt * 64) * DD);
            #pragma unroll
            for (int s = 0; s < 4; s++) {
                int f = tid + s * 256;
                int r = f >> 4, c4 = f & 15;
                *(float4*)(k_s + r * 68 + c4 * 4) = tf32r4(k4[f]);
            }
        }
        __syncthreads();

        float acc[4][4];
        #pragma unroll
        for (int nt = 0; nt < 4; nt++)
            #pragma unroll
            for (int x = 0; x < 4; x++) acc[nt][x] = 0.f;

        #pragma unroll
        for (int ks = 0; ks < 8; ks++) {
            // A-fragments reloaded per tile (keeps live regs low -> no spills)
            const float* qa = q_s + (mrow + gid) * 68 + ks * 8 + tid4;
            unsigned a0 = __float_as_uint(qa[0]);
            unsigned a1 = __float_as_uint(qa[8 * 68]);
            unsigned a2 = __float_as_uint(qa[4]);
            unsigned a3 = __float_as_uint(qa[8 * 68 + 4]);
            #pragma unroll
            for (int nt = 0; nt < 4; nt++) {
                const float* kb = k_s + (ncol + nt * 8 + gid) * 68 + ks * 8 + tid4;
                unsigned b0 = __float_as_uint(kb[0]);
                unsigned b1 = __float_as_uint(kb[4]);
                MMA_TF32(acc[nt][0], acc[nt][1], acc[nt][2], acc[nt][3],
                         a0, a1, a2, a3, b0, b1);
            }
        }

        #pragma unroll
        for (int nt = 0; nt < 4; nt++) {
            int jg = jt * 64 + ncol + nt * 8 + tid4 * 2;
            float2 wl = *(const float2*)(gw + row_lo + jg);
            float2 wh = *(const float2*)(gw + row_hi + jg);
            uchar2 ml = *(const uchar2*)(gmask + row_lo + jg);
            uchar2 mh = *(const uchar2*)(gmask + row_hi + jg);
            int pj0 = posa[jg], pj1 = posa[jg + 1];
            int d00 = max(-64, min(64, pj0 - pil)) + 64;
            int d01 = max(-64, min(64, pj1 - pil)) + 64;
            int d10 = max(-64, min(64, pj0 - pih)) + 64;
            int d11 = max(-64, min(64, pj1 - pih)) + 64;
            float s00 = (acc[nt][0] + qe_s[(mrow + gid)     * QESTR + d00] + wl.x) * 0.125f;
            float s01 = (acc[nt][1] + qe_s[(mrow + gid)     * QESTR + d01] + wl.y) * 0.125f;
            float s10 = (acc[nt][2] + qe_s[(mrow + gid + 8) * QESTR + d10] + wh.x) * 0.125f;
            float s11 = (acc[nt][3] + qe_s[(mrow + gid + 8) * QESTR + d11] + wh.y) * 0.125f;
            if (ml.x) s00 = -INFINITY;
            if (ml.y) s01 = -INFINITY;
            if (mh.x) s10 = -INFINITY;
            if (mh.y) s11 = -INFINITY;
            *(float2*)(g_scores + row_lo + jg) = make_float2(s00, s01);
            *(float2*)(g_scores + row_hi + jg) = make_float2(s10, s11);
        }
        __syncthreads();
    }
}

// ============ K_softmax: softmax rows -> p + fixed-point av scatter ============
extern "C" __global__ void __launch_bounds__(256, 3)
softmax_kernel(const int* __restrict__ gpos, float* __restrict__ gp)
{
    __shared__ int posa[LL];
    __shared__ unsigned long long a64s[8 * 264];

    const int b    = blockIdx.y;
    const int i    = blockIdx.x * 8 + (threadIdx.x >> 5);   // row per warp
    const int lane = threadIdx.x & 31;
    const int warp = threadIdx.x >> 5;
    const unsigned FULL = 0xffffffffu;

    #pragma unroll
    for (int t = threadIdx.x; t < LL; t += 256) posa[t] = gpos[b * LL + t];
    __syncthreads();

    float* pdst = gp ? gp : g_scores;
    const size_t grow = ((size_t)b * LL + i) * LL;
    const float4* s4 = (const float4*)(g_scores + grow);

    float4 r4[8];
    #pragma unroll
    for (int c = 0; c < 8; c++) r4[c] = s4[lane + 32 * c];

    float m = -INFINITY;
    #pragma unroll
    for (int c = 0; c < 8; c++)
        m = fmaxf(m, fmaxf(fmaxf(r4[c].x, r4[c].y), fmaxf(r4[c].z, r4[c].w)));
    #pragma unroll
    for (int o = 16; o > 0; o >>= 1) m = fmaxf(m, __shfl_xor_sync(FULL, m, o));

    float sum = 0.f;
    #pragma unroll
    for (int c = 0; c < 8; c++) {
        r4[c].x = __expf(r4[c].x - m); sum += r4[c].x;
        r4[c].y = __expf(r4[c].y - m); sum += r4[c].y;
        r4[c].z = __expf(r4[c].z - m); sum += r4[c].z;
        r4[c].w = __expf(r4[c].w - m); sum += r4[c].w;
    }
    #pragma unroll
    for (int o = 16; o > 0; o >>= 1) sum += __shfl_xor_sync(FULL, sum, o);
    float inv = 1.0f / sum;

    unsigned long long* a64 = a64s + (size_t)warp * 264;
    #pragma unroll
    for (int c = 0; c < 9; c++) {
        int idx = lane + 32 * c;
        if (idx < 264) a64[idx] = 0ull;
    }
    __syncwarp();

    const int pi = posa[i];
    const int bank = lane & 1;
    float4* p4 = (float4*)(pdst + grow);
    #pragma unroll
    for (int c = 0; c < 8; c++) {
        float4 pv;
        pv.x = r4[c].x * inv; pv.y = r4[c].y * inv;
        pv.z = r4[c].z * inv; pv.w = r4[c].w * inv;
        p4[lane + 32 * c] = pv;
        int j0 = (lane + 32 * c) * 4;
        int df0 = max(-64, min(64, posa[j0    ] - pi)) + 64;
        int df1 = max(-64, min(64, posa[j0 + 1] - pi)) + 64;
        int df2 = max(-64, min(64, posa[j0 + 2] - pi)) + 64;
        int df3 = max(-64, min(64, posa[j0 + 3] - pi)) + 64;
        atomicAdd(a64 + df0 * 2 + bank, (unsigned long long)(pv.x * FIX_SCALE));
        atomicAdd(a64 + df1 * 2 + bank, (unsigned long long)(pv.y * FIX_SCALE));
        atomicAdd(a64 + df2 * 2 + bank, (unsigned long long)(pv.z * FIX_SCALE));
        atomicAdd(a64 + df3 * 2 + bank, (unsigned long long)(pv.w * FIX_SCALE));
    }
    __syncwarp();

    float* avout = g_av + ((size_t)b * LL + i) * AVG;
    #pragma unroll
    for (int c = 0; c < 6; c++) {
        int idx = lane + 32 * c;
        float val = 0.f;
        if (idx < RR)
            val = __ull2float_rn(a64[idx * 2] + a64[idx * 2 + 1]) * FIX_INV;
        avout[idx] = val;
    }
}

// ===================== K_pv: out = p @ v + av @ emb_v =====================
#define NT2 256

extern "C" __global__ void __launch_bounds__(NT2, 4)
pv_kernel(const float* __restrict__ gp_in, const float* __restrict__ gv,
          const float* __restrict__ gev, float* __restrict__ gout)
{
    __shared__ float ps2[64 * 68];
    __shared__ float vs2[64 * 72];

    const int b    = blockIdx.y;
    const int i0b  = blockIdx.x * 64;
    const int tid  = threadIdx.x;
    const int lane = tid & 31;
    const int warp = tid >> 5;
    const int gid  = lane >> 2;
    const int tid4 = lane & 3;
    const int mrow = (warp & 3) * 16;
    const int ncol = (warp >> 2) * 32;

    const float* psrc = gp_in ? gp_in : g_scores;

    float acc[4][4];
    #pragma unroll
    for (int nt = 0; nt < 4; nt++)
        #pragma unroll
        for (int x = 0; x < 4; x++) acc[nt][x] = 0.f;

    for (int t = 0; t < 19; t++) {
        if (t < 16) {
            const float4* pa = (const float4*)(psrc + ((size_t)b * LL + i0b) * LL + t * 64);
            const float4* va = (const float4*)(gv + ((size_t)b * LL + t * 64) * DD);
            #pragma unroll
            for (int s = 0; s < 4; s++) {
                int f = tid + s * NT2;
                int r = f >> 4, c4 = f & 15;
                *(float4*)(ps2 + r * 68 + c4 * 4) = tf32r4(pa[r * 256 + c4]);
                *(float4*)(vs2 + r * 72 + c4 * 4) = tf32r4(va[f]);
            }
        } else {
            int kc = t - 16;
            const float4* aa = (const float4*)(g_av + ((size_t)b * LL + i0b) * AVG + kc * 64);
            #pragma unroll
            for (int s = 0; s < 4; s++) {
                int f = tid + s * NT2;
                int r = f >> 4, c4 = f & 15;
                *(float4*)(ps2 + r * 68 + c4 * 4) = tf32r4(aa[r * (AVG/4) + c4]);
                int kr = kc * 64 + r;
                float4 ev = make_float4(0.f, 0.f, 0.f, 0.f);
                if (kr < RR)
                    ev = tf32r4(((const float4*)(gev + kr * DD))[c4]);
                *(float4*)(vs2 + r * 72 + c4 * 4) = ev;
            }
        }
        __syncthreads();

        #pragma unroll
        for (int ks = 0; ks < 8; ks++) {
            unsigned a0 = __float_as_uint(ps2[(mrow + gid)     * 68 + ks * 8 + tid4    ]);
            unsigned a1 = __float_as_uint(ps2[(mrow + gid + 8) * 68 + ks * 8 + tid4    ]);
            unsigned a2 = __float_as_uint(ps2[(mrow + gid)     * 68 + ks * 8 + tid4 + 4]);
            unsigned a3 = __float_as_uint(ps2[(mrow + gid + 8) * 68 + ks * 8 + tid4 + 4]);
            #pragma unroll
            for (int nt = 0; nt < 4; nt++) {
                unsigned b0 = __float_as_uint(vs2[(ks * 8 + tid4)     * 72 + ncol + nt * 8 + gid]);
                unsigned b1 = __float_as_uint(vs2[(ks * 8 + tid4 + 4) * 72 + ncol + nt * 8 + gid]);
                MMA_TF32(acc[nt][0], acc[nt][1], acc[nt][2], acc[nt][3],
                         a0, a1, a2, a3, b0, b1);
            }
        }
        __syncthreads();
    }

    #pragma unroll
    for (int nt = 0; nt < 4; nt++) {
        int col = ncol + nt * 8 + tid4 * 2;
        *(float2*)(gout + ((size_t)b * LL + i0b + mrow + gid)     * DD + col) =
            make_float2(acc[nt][0], acc[nt][1]);
        *(float2*)(gout + ((size_t)b * LL + i0b + mrow + gid + 8) * DD + col) =
            make_float2(acc[nt][2], acc[nt][3]);
    }
}

extern "C" void kernel_launch(void* const* d_in, const int* in_sizes, int n_in,
                              void* d_out, int out_size)
{
    const float* q   = (const float*)d_in[0];
    const float* k   = (const float*)d_in[1];
    const float* v   = (const float*)d_in[2];
    const float* w   = (const float*)d_in[3];
    const float* ek  = (const float*)d_in[4];
    const float* ev  = (const float*)d_in[5];
    const int*   pos = (const int*)d_in[6];
    const unsigned char* mask = (const unsigned char*)d_in[7];

    const long OUT_N = (long)BNH * LL * DD;   // 2,097,152
    const long P_N   = (long)BNH * LL * LL;   // 33,554,432

    float* outp = nullptr;
    float* pp   = nullptr;
    if ((long)out_size == OUT_N) {
        outp = (float*)d_out;
    } else if ((long)out_size == P_N) {
        pp = (float*)d_out;
    } else {
        outp = (float*)d_out;
        pp   = (float*)d_out + OUT_N;
    }

    cudaFuncSetAttribute(qe_kernel,
                         cudaFuncAttributeMaxDynamicSharedMemorySize, QE_SMEM);
    cudaFuncSetAttribute(score_kernel,
                         cudaFuncAttributeMaxDynamicSharedMemorySize, SC_SMEM);

    dim3 grid(LL / 64, BNH);                  // (16, 32)
    qe_kernel<<<grid, 256, QE_SMEM>>>(q, ek);
    score_kernel<<<grid, 256, SC_SMEM>>>(q, k, w, pos, mask);
    dim3 gridS(LL / 8, BNH);                  // (128, 32)
    softmax_kernel<<<gridS, 256>>>(pos, pp);
    if (outp)
        pv_kernel<<<grid, NT2>>>(pp, v, ev, outp);
}

// round 14
// speedup vs baseline: 1.5243x; 1.0413x over previous
#include <cuda_runtime.h>
#include <math.h>

#define BNH 32
#define LL  1024
#define DD  64
#define RR  129
#define AVG 192      // g_av stride (cols 129..191 zero)
#define QEG 136      // g_qe stride

__device__ float g_av[(size_t)BNH * LL * AVG];        // 25 MB
__device__ float g_qe[(size_t)BNH * LL * QEG];        // 17.8 MB
__device__ float g_scores[(size_t)BNH * LL * LL];     // 128 MB raw QK^T (+ p scratch if gp null)

#define FIX_SCALE 4503599627370496.0f   /* 2^52 */
#define FIX_INV   (1.0f / 4503599627370496.0f)

__device__ __forceinline__ unsigned tf32b(float x) {
    unsigned u;
    asm("cvt.rna.tf32.f32 %0, %1;" : "=r"(u) : "f"(x));
    return u;
}
__device__ __forceinline__ float tf32r(float x) { return __uint_as_float(tf32b(x)); }
__device__ __forceinline__ float4 tf32r4(float4 a) {
    a.x = tf32r(a.x); a.y = tf32r(a.y); a.z = tf32r(a.z); a.w = tf32r(a.w);
    return a;
}

#define MMA_TF32(c0,c1,c2,c3,a0,a1,a2,a3,b0,b1)                               \
    asm volatile("mma.sync.aligned.m16n8k8.row.col.f32.tf32.tf32.f32 "        \
                 "{%0,%1,%2,%3}, {%4,%5,%6,%7}, {%8,%9}, {%0,%1,%2,%3};"      \
                 : "+f"(c0), "+f"(c1), "+f"(c2), "+f"(c3)                      \
                 : "r"(a0), "r"(a1), "r"(a2), "r"(a3), "r"(b0), "r"(b1))

// ===================== K_qe: g_qe = q . emb_k^T =====================
#define QE_SMEM ((4352 + 9248) * 4)

extern "C" __global__ void __launch_bounds__(256)
qe_kernel(const float* __restrict__ gq, const float* __restrict__ gek)
{
    extern __shared__ float sm[];
    float* q_s = sm;            // 64 x 68
    float* ek  = sm + 4352;     // 136 x 68 (rows >=129 zero)

    const int b    = blockIdx.y;
    const int i0   = blockIdx.x * 64;
    const int tid  = threadIdx.x;
    const int lane = tid & 31;
    const int warp = tid >> 5;
    const int gid  = lane >> 2;
    const int tid4 = lane & 3;

    {
        const float4* q4 = (const float4*)(gq + ((size_t)b * LL + i0) * DD);
        #pragma unroll
        for (int s = 0; s < 4; s++) {
            int f = tid + s * 256;
            int r = f >> 4, c4 = f & 15;
            *(float4*)(q_s + r * 68 + c4 * 4) = tf32r4(q4[f]);
        }
        for (int e = tid; e < 136 * 64; e += 256) {
            int r = e >> 6, d = e & 63;
            ek[r * 68 + d] = (r < RR) ? tf32r(gek[r * 64 + d]) : 0.f;
        }
    }
    __syncthreads();

    for (int t = warp; t < 68; t += 8) {
        int mt = t / 17, nt = t % 17;
        float c0 = 0.f, c1 = 0.f, c2 = 0.f, c3 = 0.f;
        #pragma unroll
        for (int ks = 0; ks < 8; ks++) {
            const float* qa = q_s + (mt * 16 + gid) * 68 + ks * 8 + tid4;
            unsigned a0 = __float_as_uint(qa[0]);
            unsigned a1 = __float_as_uint(qa[8 * 68]);
            unsigned a2 = __float_as_uint(qa[4]);
            unsigned a3 = __float_as_uint(qa[8 * 68 + 4]);
            const float* kb = ek + (nt * 8 + gid) * 68 + ks * 8 + tid4;
            unsigned b0 = __float_as_uint(kb[0]);
            unsigned b1 = __float_as_uint(kb[4]);
            MMA_TF32(c0, c1, c2, c3, a0, a1, a2, a3, b0, b1);
        }
        int col = nt * 8 + tid4 * 2;
        float* o_lo = g_qe + ((size_t)b * LL + i0 + mt * 16 + gid) * QEG + col;
        *(float2*)o_lo            = make_float2(c0, c1);
        *(float2*)(o_lo + 8*QEG)  = make_float2(c2, c3);
    }
}

// ============ K_score: pure GEMM, raw scores = Q K^T ============
extern "C" __global__ void __launch_bounds__(256, 4)
score_kernel(const float* __restrict__ gq, const float* __restrict__ gk)
{
    __shared__ float q_s[64 * 68];
    __shared__ float k_s[64 * 68];

    const int b    = blockIdx.y;
    const int i0   = blockIdx.x * 64;
    const int tid  = threadIdx.x;
    const int lane = tid & 31;
    const int warp = tid >> 5;          // 0..7
    const int gid  = lane >> 2;
    const int tid4 = lane & 3;
    const int mrow = (warp & 3) * 16;
    const int ncol = (warp >> 2) * 32;

    {
        const float4* q4 = (const float4*)(gq + ((size_t)b * LL + i0) * DD);
        #pragma unroll
        for (int s = 0; s < 4; s++) {
            int f = tid + s * 256;
            int r = f >> 4, c4 = f & 15;
            *(float4*)(q_s + r * 68 + c4 * 4) = tf32r4(q4[f]);
        }
    }
    __syncthreads();

    const size_t row_lo = ((size_t)b * LL + i0 + mrow + gid) * LL;
    const size_t row_hi = row_lo + 8 * LL;

    for (int jt = 0; jt < 16; jt++) {
        {
            const float4* k4 = (const float4*)(gk + ((size_t)b * LL + jt * 64) * DD);
            #pragma unroll
            for (int s = 0; s < 4; s++) {
                int f = tid + s * 256;
                int r = f >> 4, c4 = f & 15;
                *(float4*)(k_s + r * 68 + c4 * 4) = tf32r4(k4[f]);
            }
        }
        __syncthreads();

        float acc[4][4];
        #pragma unroll
        for (int nt = 0; nt < 4; nt++)
            #pragma unroll
            for (int x = 0; x < 4; x++) acc[nt][x] = 0.f;

        #pragma unroll
        for (int ks = 0; ks < 8; ks++) {
            const float* qa = q_s + (mrow + gid) * 68 + ks * 8 + tid4;
            unsigned a0 = __float_as_uint(qa[0]);
            unsigned a1 = __float_as_uint(qa[8 * 68]);
            unsigned a2 = __float_as_uint(qa[4]);
            unsigned a3 = __float_as_uint(qa[8 * 68 + 4]);
            #pragma unroll
            for (int nt = 0; nt < 4; nt++) {
                const float* kb = k_s + (ncol + nt * 8 + gid) * 68 + ks * 8 + tid4;
                unsigned b0 = __float_as_uint(kb[0]);
                unsigned b1 = __float_as_uint(kb[4]);
                MMA_TF32(acc[nt][0], acc[nt][1], acc[nt][2], acc[nt][3],
                         a0, a1, a2, a3, b0, b1);
            }
        }

        #pragma unroll
        for (int nt = 0; nt < 4; nt++) {
            int jg = jt * 64 + ncol + nt * 8 + tid4 * 2;
            *(float2*)(g_scores + row_lo + jg) = make_float2(acc[nt][0], acc[nt][1]);
            *(float2*)(g_scores + row_hi + jg) = make_float2(acc[nt][2], acc[nt][3]);
        }
        __syncthreads();
    }
}

// ======== K_softmax: (raw + qe[table] + w)/8, mask -> softmax -> p + av ========
extern "C" __global__ void __launch_bounds__(256, 3)
softmax_kernel(const float* __restrict__ gw, const int* __restrict__ gpos,
               const unsigned char* __restrict__ gmask, float* __restrict__ gp)
{
    __shared__ int posa[LL];
    __shared__ float qe_sm[8][132];
    __shared__ unsigned long long a64s[8 * 264];

    const int b    = blockIdx.y;
    const int i8   = blockIdx.x * 8;
    const int lane = threadIdx.x & 31;
    const int warp = threadIdx.x >> 5;
    const int i    = i8 + warp;                 // row per warp
    const unsigned FULL = 0xffffffffu;

    #pragma unroll
    for (int t = threadIdx.x; t < LL; t += 256) posa[t] = gpos[b * LL + t];
    // stage qe rows for the 8 rows of this CTA (coalesced float4)
    for (int idx = threadIdx.x; idx < 8 * 33; idx += 256) {
        int r = idx / 33, c4 = idx % 33;
        *(float4*)(&qe_sm[r][c4 * 4]) =
            *(const float4*)(g_qe + ((size_t)b * LL + i8 + r) * QEG + c4 * 4);
    }
    __syncthreads();

    float* pdst = gp ? gp : g_scores;
    const size_t grow = ((size_t)b * LL + i) * LL;
    const float4*  s4 = (const float4*)(g_scores + grow);
    const float4*  w4 = (const float4*)(gw + grow);
    const uchar4*  m4 = (const uchar4*)(gmask + grow);
    const int pi = posa[i];
    const float* qe = qe_sm[warp];

    float4 r4[8];
    float m = -INFINITY;
    #pragma unroll
    for (int c = 0; c < 8; c++) {
        int l4 = lane + 32 * c;
        float4 s = s4[l4];
        float4 w = w4[l4];
        uchar4 mk = m4[l4];
        int j0 = l4 * 4;
        int df0 = max(-64, min(64, posa[j0    ] - pi)) + 64;
        int df1 = max(-64, min(64, posa[j0 + 1] - pi)) + 64;
        int df2 = max(-64, min(64, posa[j0 + 2] - pi)) + 64;
        int df3 = max(-64, min(64, posa[j0 + 3] - pi)) + 64;
        s.x = (s.x + qe[df0] + w.x) * 0.125f;
        s.y = (s.y + qe[df1] + w.y) * 0.125f;
        s.z = (s.z + qe[df2] + w.z) * 0.125f;
        s.w = (s.w + qe[df3] + w.w) * 0.125f;
        if (mk.x) s.x = -INFINITY;
        if (mk.y) s.y = -INFINITY;
        if (mk.z) s.z = -INFINITY;
        if (mk.w) s.w = -INFINITY;
        r4[c] = s;
        m = fmaxf(m, fmaxf(fmaxf(s.x, s.y), fmaxf(s.z, s.w)));
    }
    #pragma unroll
    for (int o = 16; o > 0; o >>= 1) m = fmaxf(m, __shfl_xor_sync(FULL, m, o));

    float sum = 0.f;
    #pragma unroll
    for (int c = 0; c < 8; c++) {
        r4[c].x = __expf(r4[c].x - m); sum += r4[c].x;
        r4[c].y = __expf(r4[c].y - m); sum += r4[c].y;
        r4[c].z = __expf(r4[c].z - m); sum += r4[c].z;
        r4[c].w = __expf(r4[c].w - m); sum += r4[c].w;
    }
    #pragma unroll
    for (int o = 16; o > 0; o >>= 1) sum += __shfl_xor_sync(FULL, sum, o);
    float inv = 1.0f / sum;

    unsigned long long* a64 = a64s + (size_t)warp * 264;
    #pragma unroll
    for (int c = 0; c < 9; c++) {
        int idx = lane + 32 * c;
        if (idx < 264) a64[idx] = 0ull;
    }
    __syncwarp();

    const int bank = lane & 1;
    float4* p4 = (float4*)(pdst + grow);
    #pragma unroll
    for (int c = 0; c < 8; c++) {
        float4 pv;
        pv.x = r4[c].x * inv; pv.y = r4[c].y * inv;
        pv.z = r4[c].z * inv; pv.w = r4[c].w * inv;
        p4[lane + 32 * c] = pv;
        int j0 = (lane + 32 * c) * 4;
        int df0 = max(-64, min(64, posa[j0    ] - pi)) + 64;
        int df1 = max(-64, min(64, posa[j0 + 1] - pi)) + 64;
        int df2 = max(-64, min(64, posa[j0 + 2] - pi)) + 64;
        int df3 = max(-64, min(64, posa[j0 + 3] - pi)) + 64;
        atomicAdd(a64 + df0 * 2 + bank, (unsigned long long)(pv.x * FIX_SCALE));
        atomicAdd(a64 + df1 * 2 + bank, (unsigned long long)(pv.y * FIX_SCALE));
        atomicAdd(a64 + df2 * 2 + bank, (unsigned long long)(pv.z * FIX_SCALE));
        atomicAdd(a64 + df3 * 2 + bank, (unsigned long long)(pv.w * FIX_SCALE));
    }
    __syncwarp();

    float* avout = g_av + ((size_t)b * LL + i) * AVG;
    #pragma unroll
    for (int c = 0; c < 6; c++) {
        int idx = lane + 32 * c;
        float val = 0.f;
        if (idx < RR)
            val = __ull2float_rn(a64[idx * 2] + a64[idx * 2 + 1]) * FIX_INV;
        avout[idx] = val;
    }
}

// ===================== K_pv: out = p @ v + av @ emb_v =====================
#define NT2 256

extern "C" __global__ void __launch_bounds__(NT2, 4)
pv_kernel(const float* __restrict__ gp_in, const float* __restrict__ gv,
          const float* __restrict__ gev, float* __restrict__ gout)
{
    __shared__ float ps2[64 * 68];
    __shared__ float vs2[64 * 72];

    const int b    = blockIdx.y;
    const int i0b  = blockIdx.x * 64;
    const int tid  = threadIdx.x;
    const int lane = tid & 31;
    const int warp = tid >> 5;
    const int gid  = lane >> 2;
    const int tid4 = lane & 3;
    const int mrow = (warp & 3) * 16;
    const int ncol = (warp >> 2) * 32;

    const float* psrc = gp_in ? gp_in : g_scores;

    float acc[4][4];
    #pragma unroll
    for (int nt = 0; nt < 4; nt++)
        #pragma unroll
        for (int x = 0; x < 4; x++) acc[nt][x] = 0.f;

    for (int t = 0; t < 19; t++) {
        if (t < 16) {
            const float4* pa = (const float4*)(psrc + ((size_t)b * LL + i0b) * LL + t * 64);
            const float4* va = (const float4*)(gv + ((size_t)b * LL + t * 64) * DD);
            #pragma unroll
            for (int s = 0; s < 4; s++) {
                int f = tid + s * NT2;
                int r = f >> 4, c4 = f & 15;
                *(float4*)(ps2 + r * 68 + c4 * 4) = tf32r4(pa[r * 256 + c4]);
                *(float4*)(vs2 + r * 72 + c4 * 4) = tf32r4(va[f]);
            }
        } else {
            int kc = t - 16;
            const float4* aa = (const float4*)(g_av + ((size_t)b * LL + i0b) * AVG + kc * 64);
            #pragma unroll
            for (int s = 0; s < 4; s++) {
                int f = tid + s * NT2;
                int r = f >> 4, c4 = f & 15;
                *(float4*)(ps2 + r * 68 + c4 * 4) = tf32r4(aa[r * (AVG/4) + c4]);
                int kr = kc * 64 + r;
                float4 ev = make_float4(0.f, 0.f, 0.f, 0.f);
                if (kr < RR)
                    ev = tf32r4(((const float4*)(gev + kr * DD))[c4]);
                *(float4*)(vs2 + r * 72 + c4 * 4) = ev;
            }
        }
        __syncthreads();

        #pragma unroll
        for (int ks = 0; ks < 8; ks++) {
            unsigned a0 = __float_as_uint(ps2[(mrow + gid)     * 68 + ks * 8 + tid4    ]);
            unsigned a1 = __float_as_uint(ps2[(mrow + gid + 8) * 68 + ks * 8 + tid4    ]);
            unsigned a2 = __float_as_uint(ps2[(mrow + gid)     * 68 + ks * 8 + tid4 + 4]);
            unsigned a3 = __float_as_uint(ps2[(mrow + gid + 8) * 68 + ks * 8 + tid4 + 4]);
            #pragma unroll
            for (int nt = 0; nt < 4; nt++) {
                unsigned b0 = __float_as_uint(vs2[(ks * 8 + tid4)     * 72 + ncol + nt * 8 + gid]);
                unsigned b1 = __float_as_uint(vs2[(ks * 8 + tid4 + 4) * 72 + ncol + nt * 8 + gid]);
                MMA_TF32(acc[nt][0], acc[nt][1], acc[nt][2], acc[nt][3],
                         a0, a1, a2, a3, b0, b1);
            }
        }
        __syncthreads();
    }

    #pragma unroll
    for (int nt = 0; nt < 4; nt++) {
        int col = ncol + nt * 8 + tid4 * 2;
        *(float2*)(gout + ((size_t)b * LL + i0b + mrow + gid)     * DD + col) =
            make_float2(acc[nt][0], acc[nt][1]);
        *(float2*)(gout + ((size_t)b * LL + i0b + mrow + gid + 8) * DD + col) =
            make_float2(acc[nt][2], acc[nt][3]);
    }
}

extern "C" void kernel_launch(void* const* d_in, const int* in_sizes, int n_in,
                              void* d_out, int out_size)
{
    const float* q   = (const float*)d_in[0];
    const float* k   = (const float*)d_in[1];
    const float* v   = (const float*)d_in[2];
    const float* w   = (const float*)d_in[3];
    const float* ek  = (const float*)d_in[4];
    const float* ev  = (const float*)d_in[5];
    const int*   pos = (const int*)d_in[6];
    const unsigned char* mask = (const unsigned char*)d_in[7];

    const long OUT_N = (long)BNH * LL * DD;   // 2,097,152
    const long P_N   = (long)BNH * LL * LL;   // 33,554,432

    float* outp = nullptr;
    float* pp   = nullptr;
    if ((long)out_size == OUT_N) {
        outp = (float*)d_out;
    } else if ((long)out_size == P_N) {
        pp = (float*)d_out;
    } else {
        outp = (float*)d_out;
        pp   = (float*)d_out + OUT_N;
    }

    cudaFuncSetAttribute(qe_kernel,
                         cudaFuncAttributeMaxDynamicSharedMemorySize, QE_SMEM);

    dim3 grid(LL / 64, BNH);                  // (16, 32)
    score_kernel<<<grid, 256>>>(q, k);
    qe_kernel<<<grid, 256, QE_SMEM>>>(q, ek);
    dim3 gridS(LL / 8, BNH);                  // (128, 32)
    softmax_kernel<<<gridS, 256>>>(w, pos, mask, pp);
    if (outp)
        pv_kernel<<<grid, NT2>>>(pp, v, ev, outp);
}

// round 15
// speedup vs baseline: 2.6820x; 1.7595x over previous
#include <cuda_runtime.h>
#include <math.h>

#define BNH 32
#define LL  1024
#define DD  64
#define RR  129
#define AVG 192      // g_av stride (cols 129..191 zero)
#define QEG 136      // g_qe stride

__device__ float g_av[(size_t)BNH * LL * AVG];        // 25 MB
__device__ float g_qe[(size_t)BNH * LL * QEG];        // 17.8 MB
__device__ float g_scores[(size_t)BNH * LL * LL];     // 128 MB raw QK^T (+ p scratch if gp null)

#define FIX_SCALE 4503599627370496.0f   /* 2^52 */
#define FIX_INV   (1.0f / 4503599627370496.0f)

__device__ __forceinline__ unsigned tf32b(float x) {
    unsigned u;
    asm("cvt.rna.tf32.f32 %0, %1;" : "=r"(u) : "f"(x));
    return u;
}
__device__ __forceinline__ float tf32r(float x) { return __uint_as_float(tf32b(x)); }
__device__ __forceinline__ float4 tf32r4(float4 a) {
    a.x = tf32r(a.x); a.y = tf32r(a.y); a.z = tf32r(a.z); a.w = tf32r(a.w);
    return a;
}

#define MMA_TF32(c0,c1,c2,c3,a0,a1,a2,a3,b0,b1)                               \
    asm volatile("mma.sync.aligned.m16n8k8.row.col.f32.tf32.tf32.f32 "        \
                 "{%0,%1,%2,%3}, {%4,%5,%6,%7}, {%8,%9}, {%0,%1,%2,%3};"      \
                 : "+f"(c0), "+f"(c1), "+f"(c2), "+f"(c3)                      \
                 : "r"(a0), "r"(a1), "r"(a2), "r"(a3), "r"(b0), "r"(b1))

// ===================== K_qe: g_qe = q . emb_k^T =====================
#define QE_SMEM ((4352 + 9248) * 4)

extern "C" __global__ void __launch_bounds__(256)
qe_kernel(const float* __restrict__ gq, const float* __restrict__ gek)
{
    extern __shared__ float sm[];
    float* q_s = sm;            // 64 x 68
    float* ek  = sm + 4352;     // 136 x 68 (rows >=129 zero)

    const int b    = blockIdx.y;
    const int i0   = blockIdx.x * 64;
    const int tid  = threadIdx.x;
    const int lane = tid & 31;
    const int warp = tid >> 5;
    const int gid  = lane >> 2;
    const int tid4 = lane & 3;

    {
        const float4* q4 = (const float4*)(gq + ((size_t)b * LL + i0) * DD);
        #pragma unroll
        for (int s = 0; s < 4; s++) {
            int f = tid + s * 256;
            int r = f >> 4, c4 = f & 15;
            *(float4*)(q_s + r * 68 + c4 * 4) = tf32r4(q4[f]);
        }
        for (int e = tid; e < 136 * 64; e += 256) {
            int r = e >> 6, d = e & 63;
            ek[r * 68 + d] = (r < RR) ? tf32r(gek[r * 64 + d]) : 0.f;
        }
    }
    __syncthreads();

    for (int t = warp; t < 68; t += 8) {
        int mt = t / 17, nt = t % 17;
        float c0 = 0.f, c1 = 0.f, c2 = 0.f, c3 = 0.f;
        #pragma unroll
        for (int ks = 0; ks < 8; ks++) {
            const float* qa = q_s + (mt * 16 + gid) * 68 + ks * 8 + tid4;
            unsigned a0 = __float_as_uint(qa[0]);
            unsigned a1 = __float_as_uint(qa[8 * 68]);
            unsigned a2 = __float_as_uint(qa[4]);
            unsigned a3 = __float_as_uint(qa[8 * 68 + 4]);
            const float* kb = ek + (nt * 8 + gid) * 68 + ks * 8 + tid4;
            unsigned b0 = __float_as_uint(kb[0]);
            unsigned b1 = __float_as_uint(kb[4]);
            MMA_TF32(c0, c1, c2, c3, a0, a1, a2, a3, b0, b1);
        }
        int col = nt * 8 + tid4 * 2;
        float* o_lo = g_qe + ((size_t)b * LL + i0 + mt * 16 + gid) * QEG + col;
        *(float2*)o_lo            = make_float2(c0, c1);
        *(float2*)(o_lo + 8*QEG)  = make_float2(c2, c3);
    }
}

// ============ K_score: pure GEMM, raw scores = Q K^T ============
extern "C" __global__ void __launch_bounds__(256, 4)
score_kernel(const float* __restrict__ gq, const float* __restrict__ gk)
{
    __shared__ float q_s[64 * 68];
    __shared__ float k_s[64 * 68];

    const int b    = blockIdx.y;
    const int i0   = blockIdx.x * 64;
    const int tid  = threadIdx.x;
    const int lane = tid & 31;
    const int warp = tid >> 5;          // 0..7
    const int gid  = lane >> 2;
    const int tid4 = lane & 3;
    const int mrow = (warp & 3) * 16;
    const int ncol = (warp >> 2) * 32;

    {
        const float4* q4 = (const float4*)(gq + ((size_t)b * LL + i0) * DD);
        #pragma unroll
        for (int s = 0; s < 4; s++) {
            int f = tid + s * 256;
            int r = f >> 4, c4 = f & 15;
            *(float4*)(q_s + r * 68 + c4 * 4) = tf32r4(q4[f]);
        }
    }
    __syncthreads();

    const size_t row_lo = ((size_t)b * LL + i0 + mrow + gid) * LL;
    const size_t row_hi = row_lo + 8 * LL;

    for (int jt = 0; jt < 16; jt++) {
        {
            const float4* k4 = (const float4*)(gk + ((size_t)b * LL + jt * 64) * DD);
            #pragma unroll
            for (int s = 0; s < 4; s++) {
                int f = tid + s * 256;
                int r = f >> 4, c4 = f & 15;
                *(float4*)(k_s + r * 68 + c4 * 4) = tf32r4(k4[f]);
            }
        }
        __syncthreads();

        float acc[4][4];
        #pragma unroll
        for (int nt = 0; nt < 4; nt++)
            #pragma unroll
            for (int x = 0; x < 4; x++) acc[nt][x] = 0.f;

        #pragma unroll
        for (int ks = 0; ks < 8; ks++) {
            const float* qa = q_s + (mrow + gid) * 68 + ks * 8 + tid4;
            unsigned a0 = __float_as_uint(qa[0]);
            unsigned a1 = __float_as_uint(qa[8 * 68]);
            unsigned a2 = __float_as_uint(qa[4]);
            unsigned a3 = __float_as_uint(qa[8 * 68 + 4]);
            #pragma unroll
            for (int nt = 0; nt < 4; nt++) {
                const float* kb = k_s + (ncol + nt * 8 + gid) * 68 + ks * 8 + tid4;
                unsigned b0 = __float_as_uint(kb[0]);
                unsigned b1 = __float_as_uint(kb[4]);
                MMA_TF32(acc[nt][0], acc[nt][1], acc[nt][2], acc[nt][3],
                         a0, a1, a2, a3, b0, b1);
            }
        }

        #pragma unroll
        for (int nt = 0; nt < 4; nt++) {
            int jg = jt * 64 + ncol + nt * 8 + tid4 * 2;
            *(float2*)(g_scores + row_lo + jg) = make_float2(acc[nt][0], acc[nt][1]);
            *(float2*)(g_scores + row_hi + jg) = make_float2(acc[nt][2], acc[nt][3]);
        }
        __syncthreads();
    }
}

// ======== K_softmax: (raw + qe[table] + w)/8, mask -> softmax -> p + av ========
// Clip buckets (df==0 / df==128) dominate (pos span 2048 >> 2*64): accumulate
// them in per-lane u64 registers + warp-reduce (exact integer adds -> bucket
// totals bit-identical to the all-atomic version); atomics only for interior.
extern "C" __global__ void __launch_bounds__(256, 3)
softmax_kernel(const float* __restrict__ gw, const int* __restrict__ gpos,
               const unsigned char* __restrict__ gmask, float* __restrict__ gp)
{
    __shared__ int posa[LL];
    __shared__ float qe_sm[8][132];
    __shared__ unsigned long long a64s[8 * 264];

    const int b    = blockIdx.y;
    const int i8   = blockIdx.x * 8;
    const int lane = threadIdx.x & 31;
    const int warp = threadIdx.x >> 5;
    const int i    = i8 + warp;                 // row per warp
    const unsigned FULL = 0xffffffffu;

    #pragma unroll
    for (int t = threadIdx.x; t < LL; t += 256) posa[t] = gpos[b * LL + t];
    // stage qe rows for the 8 rows of this CTA (coalesced float4)
    for (int idx = threadIdx.x; idx < 8 * 33; idx += 256) {
        int r = idx / 33, c4 = idx % 33;
        *(float4*)(&qe_sm[r][c4 * 4]) =
            *(const float4*)(g_qe + ((size_t)b * LL + i8 + r) * QEG + c4 * 4);
    }
    __syncthreads();

    float* pdst = gp ? gp : g_scores;
    const size_t grow = ((size_t)b * LL + i) * LL;
    const float4*  s4 = (const float4*)(g_scores + grow);
    const float4*  w4 = (const float4*)(gw + grow);
    const uchar4*  m4 = (const uchar4*)(gmask + grow);
    const int pi = posa[i];
    const float* qe = qe_sm[warp];

    // precompute clipped bucket indices (reused for scatter)
    int dfr[8][4];
    float4 r4[8];
    float m = -INFINITY;
    #pragma unroll
    for (int c = 0; c < 8; c++) {
        int l4 = lane + 32 * c;
        float4 s = s4[l4];
        float4 w = w4[l4];
        uchar4 mk = m4[l4];
        int j0 = l4 * 4;
        int df0 = max(-64, min(64, posa[j0    ] - pi)) + 64;
        int df1 = max(-64, min(64, posa[j0 + 1] - pi)) + 64;
        int df2 = max(-64, min(64, posa[j0 + 2] - pi)) + 64;
        int df3 = max(-64, min(64, posa[j0 + 3] - pi)) + 64;
        dfr[c][0] = df0; dfr[c][1] = df1; dfr[c][2] = df2; dfr[c][3] = df3;
        s.x = (s.x + qe[df0] + w.x) * 0.125f;
        s.y = (s.y + qe[df1] + w.y) * 0.125f;
        s.z = (s.z + qe[df2] + w.z) * 0.125f;
        s.w = (s.w + qe[df3] + w.w) * 0.125f;
        if (mk.x) s.x = -INFINITY;
        if (mk.y) s.y = -INFINITY;
        if (mk.z) s.z = -INFINITY;
        if (mk.w) s.w = -INFINITY;
        r4[c] = s;
        m = fmaxf(m, fmaxf(fmaxf(s.x, s.y), fmaxf(s.z, s.w)));
    }
    #pragma unroll
    for (int o = 16; o > 0; o >>= 1) m = fmaxf(m, __shfl_xor_sync(FULL, m, o));

    float sum = 0.f;
    #pragma unroll
    for (int c = 0; c < 8; c++) {
        r4[c].x = __expf(r4[c].x - m); sum += r4[c].x;
        r4[c].y = __expf(r4[c].y - m); sum += r4[c].y;
        r4[c].z = __expf(r4[c].z - m); sum += r4[c].z;
        r4[c].w = __expf(r4[c].w - m); sum += r4[c].w;
    }
    #pragma unroll
    for (int o = 16; o > 0; o >>= 1) sum += __shfl_xor_sync(FULL, sum, o);
    float inv = 1.0f / sum;

    unsigned long long* a64 = a64s + (size_t)warp * 264;
    #pragma unroll
    for (int c = 0; c < 9; c++) {
        int idx = lane + 32 * c;
        if (idx < 264) a64[idx] = 0ull;
    }
    __syncwarp();

    const int bank = lane & 1;
    unsigned long long acc_lo = 0ull, acc_hi = 0ull;   // df==0 / df==128
    float4* p4 = (float4*)(pdst + grow);
    #pragma unroll
    for (int c = 0; c < 8; c++) {
        float4 pv;
        pv.x = r4[c].x * inv; pv.y = r4[c].y * inv;
        pv.z = r4[c].z * inv; pv.w = r4[c].w * inv;
        p4[lane + 32 * c] = pv;
        unsigned long long qv;
        #define SCATTER1(PV, DF)                                             \
            qv = (unsigned long long)((PV) * FIX_SCALE);                     \
            if ((DF) == 0)        acc_lo += qv;                              \
            else if ((DF) == 128) acc_hi += qv;                              \
            else atomicAdd(a64 + (DF) * 2 + bank, qv);
        SCATTER1(pv.x, dfr[c][0])
        SCATTER1(pv.y, dfr[c][1])
        SCATTER1(pv.z, dfr[c][2])
        SCATTER1(pv.w, dfr[c][3])
        #undef SCATTER1
    }
    // exact u64 warp reduction of the two clip buckets
    #pragma unroll
    for (int o = 16; o > 0; o >>= 1) {
        acc_lo += __shfl_xor_sync(FULL, acc_lo, o);
        acc_hi += __shfl_xor_sync(FULL, acc_hi, o);
    }
    if (lane == 0) {
        a64[0]       += acc_lo;
        a64[128 * 2] += acc_hi;
    }
    __syncwarp();

    float* avout = g_av + ((size_t)b * LL + i) * AVG;
    #pragma unroll
    for (int c = 0; c < 6; c++) {
        int idx = lane + 32 * c;
        float val = 0.f;
        if (idx < RR)
            val = __ull2float_rn(a64[idx * 2] + a64[idx * 2 + 1]) * FIX_INV;
        avout[idx] = val;
    }
}

// ===================== K_pv: out = p @ v + av @ emb_v =====================
#define NT2 256

extern "C" __global__ void __launch_bounds__(NT2, 4)
pv_kernel(const float* __restrict__ gp_in, const float* __restrict__ gv,
          const float* __restrict__ gev, float* __restrict__ gout)
{
    __shared__ float ps2[64 * 68];
    __shared__ float vs2[64 * 72];

    const int b    = blockIdx.y;
    const int i0b  = blockIdx.x * 64;
    const int tid  = threadIdx.x;
    const int lane = tid & 31;
    const int warp = tid >> 5;
    const int gid  = lane >> 2;
    const int tid4 = lane & 3;
    const int mrow = (warp & 3) * 16;
    const int ncol = (warp >> 2) * 32;

    const float* psrc = gp_in ? gp_in : g_scores;

    float acc[4][4];
    #pragma unroll
    for (int nt = 0; nt < 4; nt++)
        #pragma unroll
        for (int x = 0; x < 4; x++) acc[nt][x] = 0.f;

    for (int t = 0; t < 19; t++) {
        if (t < 16) {
            const float4* pa = (const float4*)(psrc + ((size_t)b * LL + i0b) * LL + t * 64);
            const float4* va = (const float4*)(gv + ((size_t)b * LL + t * 64) * DD);
            #pragma unroll
            for (int s = 0; s < 4; s++) {
                int f = tid + s * NT2;
                int r = f >> 4, c4 = f & 15;
                *(float4*)(ps2 + r * 68 + c4 * 4) = tf32r4(pa[r * 256 + c4]);
                *(float4*)(vs2 + r * 72 + c4 * 4) = tf32r4(va[f]);
            }
        } else {
            int kc = t - 16;
            const float4* aa = (const float4*)(g_av + ((size_t)b * LL + i0b) * AVG + kc * 64);
            #pragma unroll
            for (int s = 0; s < 4; s++) {
                int f = tid + s * NT2;
                int r = f >> 4, c4 = f & 15;
                *(float4*)(ps2 + r * 68 + c4 * 4) = tf32r4(aa[r * (AVG/4) + c4]);
                int kr = kc * 64 + r;
                float4 ev = make_float4(0.f, 0.f, 0.f, 0.f);
                if (kr < RR)
                    ev = tf32r4(((const float4*)(gev + kr * DD))[c4]);
                *(float4*)(vs2 + r * 72 + c4 * 4) = ev;
            }
        }
        __syncthreads();

        #pragma unroll
        for (int ks = 0; ks < 8; ks++) {
            unsigned a0 = __float_as_uint(ps2[(mrow + gid)     * 68 + ks * 8 + tid4    ]);
            unsigned a1 = __float_as_uint(ps2[(mrow + gid + 8) * 68 + ks * 8 + tid4    ]);
            unsigned a2 = __float_as_uint(ps2[(mrow + gid)     * 68 + ks * 8 + tid4 + 4]);
            unsigned a3 = __float_as_uint(ps2[(mrow + gid + 8) * 68 + ks * 8 + tid4 + 4]);
            #pragma unroll
            for (int nt = 0; nt < 4; nt++) {
                unsigned b0 = __float_as_uint(vs2[(ks * 8 + tid4)     * 72 + ncol + nt * 8 + gid]);
                unsigned b1 = __float_as_uint(vs2[(ks * 8 + tid4 + 4) * 72 + ncol + nt * 8 + gid]);
                MMA_TF32(acc[nt][0], acc[nt][1], acc[nt][2], acc[nt][3],
                         a0, a1, a2, a3, b0, b1);
            }
        }
        __syncthreads();
    }

    #pragma unroll
    for (int nt = 0; nt < 4; nt++) {
        int col = ncol + nt * 8 + tid4 * 2;
        *(float2*)(gout + ((size_t)b * LL + i0b + mrow + gid)     * DD + col) =
            make_float2(acc[nt][0], acc[nt][1]);
        *(float2*)(gout + ((size_t)b * LL + i0b + mrow + gid + 8) * DD + col) =
            make_float2(acc[nt][2], acc[nt][3]);
    }
}

extern "C" void kernel_launch(void* const* d_in, const int* in_sizes, int n_in,
                              void* d_out, int out_size)
{
    const float* q   = (const float*)d_in[0];
    const float* k   = (const float*)d_in[1];
    const float* v   = (const float*)d_in[2];
    const float* w   = (const float*)d_in[3];
    const float* ek  = (const float*)d_in[4];
    const float* ev  = (const float*)d_in[5];
    const int*   pos = (const int*)d_in[6];
    const unsigned char* mask = (const unsigned char*)d_in[7];

    const long OUT_N = (long)BNH * LL * DD;   // 2,097,152
    const long P_N   = (long)BNH * LL * LL;   // 33,554,432

    float* outp = nullptr;
    float* pp   = nullptr;
    if ((long)out_size == OUT_N) {
        outp = (float*)d_out;
    } else if ((long)out_size == P_N) {
        pp = (float*)d_out;
    } else {
        outp = (float*)d_out;
        pp   = (float*)d_out + OUT_N;
    }

    cudaFuncSetAttribute(qe_kernel,
                         cudaFuncAttributeMaxDynamicSharedMemorySize, QE_SMEM);

    dim3 grid(LL / 64, BNH);                  // (16, 32)
    score_kernel<<<grid, 256>>>(q, k);
    qe_kernel<<<grid, 256, QE_SMEM>>>(q, ek);
    dim3 gridS(LL / 8, BNH);                  // (128, 32)
    softmax_kernel<<<gridS, 256>>>(w, pos, mask, pp);
    if (outp)
        pv_kernel<<<grid, NT2>>>(pp, v, ev, outp);
}

// round 16
// speedup vs baseline: 2.7217x; 1.0148x over previous
#include <cuda_runtime.h>
#include <math.h>

#define BNH 32
#define LL  1024
#define DD  64
#define RR  129
#define AVG 192      // g_av stride (cols 129..191 zero)
#define QEG 136      // g_qe stride

__device__ float g_av[(size_t)BNH * LL * AVG];        // 25 MB
__device__ float g_qe[(size_t)BNH * LL * QEG];        // 17.8 MB
__device__ float g_scores[(size_t)BNH * LL * LL];     // 128 MB raw QK^T (+ p scratch if gp null)

#define FIX_SCALE 4503599627370496.0f   /* 2^52 */
#define FIX_INV   (1.0f / 4503599627370496.0f)

__device__ __forceinline__ unsigned tf32b(float x) {
    unsigned u;
    asm("cvt.rna.tf32.f32 %0, %1;" : "=r"(u) : "f"(x));
    return u;
}
__device__ __forceinline__ float tf32r(float x) { return __uint_as_float(tf32b(x)); }
__device__ __forceinline__ float4 tf32r4(float4 a) {
    a.x = tf32r(a.x); a.y = tf32r(a.y); a.z = tf32r(a.z); a.w = tf32r(a.w);
    return a;
}

#define MMA_TF32(c0,c1,c2,c3,a0,a1,a2,a3,b0,b1)                               \
    asm volatile("mma.sync.aligned.m16n8k8.row.col.f32.tf32.tf32.f32 "        \
                 "{%0,%1,%2,%3}, {%4,%5,%6,%7}, {%8,%9}, {%0,%1,%2,%3};"      \
                 : "+f"(c0), "+f"(c1), "+f"(c2), "+f"(c3)                      \
                 : "r"(a0), "r"(a1), "r"(a2), "r"(a3), "r"(b0), "r"(b1))

// ============ K_score_qe: grid-fused score GEMM (x<16) + qe GEMM (x>=16) ============
// dynamic smem: 4352 + 9248 floats = 54400 B
#define SQ_SMEM ((4352 + 9248) * 4)

extern "C" __global__ void __launch_bounds__(256, 4)
score_qe_kernel(const float* __restrict__ gq, const float* __restrict__ gk,
                const float* __restrict__ gek)
{
    extern __shared__ float sm[];
    const int bx   = blockIdx.x;
    const int b    = blockIdx.y;
    const int tid  = threadIdx.x;
    const int lane = tid & 31;
    const int warp = tid >> 5;
    const int gid  = lane >> 2;
    const int tid4 = lane & 3;

    if (bx < 16) {
        // ---------------- score body: raw scores = Q K^T ----------------
        float* q_s = sm;             // 64 x 68
        float* k_s = sm + 4352;      // 64 x 68
        const int i0   = bx * 64;
        const int mrow = (warp & 3) * 16;
        const int ncol = (warp >> 2) * 32;

        {
            const float4* q4 = (const float4*)(gq + ((size_t)b * LL + i0) * DD);
            #pragma unroll
            for (int s = 0; s < 4; s++) {
                int f = tid + s * 256;
                int r = f >> 4, c4 = f & 15;
                *(float4*)(q_s + r * 68 + c4 * 4) = tf32r4(q4[f]);
            }
        }
        __syncthreads();

        const size_t row_lo = ((size_t)b * LL + i0 + mrow + gid) * LL;
        const size_t row_hi = row_lo + 8 * LL;

        for (int jt = 0; jt < 16; jt++) {
            {
                const float4* k4 = (const float4*)(gk + ((size_t)b * LL + jt * 64) * DD);
                #pragma unroll
                for (int s = 0; s < 4; s++) {
                    int f = tid + s * 256;
                    int r = f >> 4, c4 = f & 15;
                    *(float4*)(k_s + r * 68 + c4 * 4) = tf32r4(k4[f]);
                }
            }
            __syncthreads();

            float acc[4][4];
            #pragma unroll
            for (int nt = 0; nt < 4; nt++)
                #pragma unroll
                for (int x = 0; x < 4; x++) acc[nt][x] = 0.f;

            #pragma unroll
            for (int ks = 0; ks < 8; ks++) {
                const float* qa = q_s + (mrow + gid) * 68 + ks * 8 + tid4;
                unsigned a0 = __float_as_uint(qa[0]);
                unsigned a1 = __float_as_uint(qa[8 * 68]);
                unsigned a2 = __float_as_uint(qa[4]);
                unsigned a3 = __float_as_uint(qa[8 * 68 + 4]);
                #pragma unroll
                for (int nt = 0; nt < 4; nt++) {
                    const float* kb = k_s + (ncol + nt * 8 + gid) * 68 + ks * 8 + tid4;
                    unsigned b0 = __float_as_uint(kb[0]);
                    unsigned b1 = __float_as_uint(kb[4]);
                    MMA_TF32(acc[nt][0], acc[nt][1], acc[nt][2], acc[nt][3],
                             a0, a1, a2, a3, b0, b1);
                }
            }

            #pragma unroll
            for (int nt = 0; nt < 4; nt++) {
                int jg = jt * 64 + ncol + nt * 8 + tid4 * 2;
                *(float2*)(g_scores + row_lo + jg) = make_float2(acc[nt][0], acc[nt][1]);
                *(float2*)(g_scores + row_hi + jg) = make_float2(acc[nt][2], acc[nt][3]);
            }
            __syncthreads();
        }
    } else {
        // ---------------- qe body: g_qe = q . emb_k^T ----------------
        float* q_s = sm;             // 64 x 68
        float* ek  = sm + 4352;      // 136 x 68 (rows >=129 zero)
        const int i0 = (bx - 16) * 64;

        {
            const float4* q4 = (const float4*)(gq + ((size_t)b * LL + i0) * DD);
            #pragma unroll
            for (int s = 0; s < 4; s++) {
                int f = tid + s * 256;
                int r = f >> 4, c4 = f & 15;
                *(float4*)(q_s + r * 68 + c4 * 4) = tf32r4(q4[f]);
            }
            for (int e = tid; e < 136 * 64; e += 256) {
                int r = e >> 6, d = e & 63;
                ek[r * 68 + d] = (r < RR) ? tf32r(gek[r * 64 + d]) : 0.f;
            }
        }
        __syncthreads();

        for (int t = warp; t < 68; t += 8) {
            int mt = t / 17, nt = t % 17;
            float c0 = 0.f, c1 = 0.f, c2 = 0.f, c3 = 0.f;
            #pragma unroll
            for (int ks = 0; ks < 8; ks++) {
                const float* qa = q_s + (mt * 16 + gid) * 68 + ks * 8 + tid4;
                unsigned a0 = __float_as_uint(qa[0]);
                unsigned a1 = __float_as_uint(qa[8 * 68]);
                unsigned a2 = __float_as_uint(qa[4]);
                unsigned a3 = __float_as_uint(qa[8 * 68 + 4]);
                const float* kb = ek + (nt * 8 + gid) * 68 + ks * 8 + tid4;
                unsigned b0 = __float_as_uint(kb[0]);
                unsigned b1 = __float_as_uint(kb[4]);
                MMA_TF32(c0, c1, c2, c3, a0, a1, a2, a3, b0, b1);
            }
            int col = nt * 8 + tid4 * 2;
            float* o_lo = g_qe + ((size_t)b * LL + i0 + mt * 16 + gid) * QEG + col;
            *(float2*)o_lo            = make_float2(c0, c1);
            *(float2*)(o_lo + 8*QEG)  = make_float2(c2, c3);
        }
    }
}

// ======== K_softmax: (raw + qe[table] + w)/8, mask -> softmax -> p + av ========
// Clip buckets (df==0 / df==128) accumulate in per-lane u64 registers + exact
// warp shfl reduce; atomics only for the ~interior buckets. 1 bank (exact ->
// bucket totals bit-identical). df recomputed in the scatter pass (reg relief).
extern "C" __global__ void __launch_bounds__(256, 4)
softmax_kernel(const float* __restrict__ gw, const int* __restrict__ gpos,
               const unsigned char* __restrict__ gmask, float* __restrict__ gp)
{
    __shared__ int posa[LL];
    __shared__ float qe_sm[8][132];
    __shared__ unsigned long long a64s[8 * 132];

    const int b    = blockIdx.y;
    const int i8   = blockIdx.x * 8;
    const int lane = threadIdx.x & 31;
    const int warp = threadIdx.x >> 5;
    const int i    = i8 + warp;                 // row per warp
    const unsigned FULL = 0xffffffffu;

    #pragma unroll
    for (int t = threadIdx.x; t < LL; t += 256) posa[t] = gpos[b * LL + t];
    for (int idx = threadIdx.x; idx < 8 * 33; idx += 256) {
        int r = idx / 33, c4 = idx % 33;
        *(float4*)(&qe_sm[r][c4 * 4]) =
            *(const float4*)(g_qe + ((size_t)b * LL + i8 + r) * QEG + c4 * 4);
    }
    __syncthreads();

    float* pdst = gp ? gp : g_scores;
    const size_t grow = ((size_t)b * LL + i) * LL;
    const float4*  s4 = (const float4*)(g_scores + grow);
    const float4*  w4 = (const float4*)(gw + grow);
    const uchar4*  m4 = (const uchar4*)(gmask + grow);
    const int pi = posa[i];
    const float* qe = qe_sm[warp];

    float4 r4[8];
    float m = -INFINITY;
    #pragma unroll
    for (int c = 0; c < 8; c++) {
        int l4 = lane + 32 * c;
        float4 s = s4[l4];
        float4 w = w4[l4];
        uchar4 mk = m4[l4];
        int4 pj = *(const int4*)(posa + l4 * 4);
        int df0 = max(-64, min(64, pj.x - pi)) + 64;
        int df1 = max(-64, min(64, pj.y - pi)) + 64;
        int df2 = max(-64, min(64, pj.z - pi)) + 64;
        int df3 = max(-64, min(64, pj.w - pi)) + 64;
        s.x = (s.x + qe[df0] + w.x) * 0.125f;
        s.y = (s.y + qe[df1] + w.y) * 0.125f;
        s.z = (s.z + qe[df2] + w.z) * 0.125f;
        s.w = (s.w + qe[df3] + w.w) * 0.125f;
        if (mk.x) s.x = -INFINITY;
        if (mk.y) s.y = -INFINITY;
        if (mk.z) s.z = -INFINITY;
        if (mk.w) s.w = -INFINITY;
        r4[c] = s;
        m = fmaxf(m, fmaxf(fmaxf(s.x, s.y), fmaxf(s.z, s.w)));
    }
    #pragma unroll
    for (int o = 16; o > 0; o >>= 1) m = fmaxf(m, __shfl_xor_sync(FULL, m, o));

    float sum = 0.f;
    #pragma unroll
    for (int c = 0; c < 8; c++) {
        r4[c].x = __expf(r4[c].x - m); sum += r4[c].x;
        r4[c].y = __expf(r4[c].y - m); sum += r4[c].y;
        r4[c].z = __expf(r4[c].z - m); sum += r4[c].z;
        r4[c].w = __expf(r4[c].w - m); sum += r4[c].w;
    }
    #pragma unroll
    for (int o = 16; o > 0; o >>= 1) sum += __shfl_xor_sync(FULL, sum, o);
    float inv = 1.0f / sum;

    unsigned long long* a64 = a64s + (size_t)warp * 132;
    #pragma unroll
    for (int c = 0; c < 5; c++) {
        int idx = lane + 32 * c;
        if (idx < 132) a64[idx] = 0ull;
    }
    __syncwarp();

    unsigned long long acc_lo = 0ull, acc_hi = 0ull;   // df==0 / df==128
    float4* p4 = (float4*)(pdst + grow);
    #pragma unroll
    for (int c = 0; c < 8; c++) {
        int l4 = lane + 32 * c;
        float4 pv;
        pv.x = r4[c].x * inv; pv.y = r4[c].y * inv;
        pv.z = r4[c].z * inv; pv.w = r4[c].w * inv;
        p4[l4] = pv;
        int4 pj = *(const int4*)(posa + l4 * 4);
        int df0 = max(-64, min(64, pj.x - pi)) + 64;
        int df1 = max(-64, min(64, pj.y - pi)) + 64;
        int df2 = max(-64, min(64, pj.z - pi)) + 64;
        int df3 = max(-64, min(64, pj.w - pi)) + 64;
        unsigned long long qv;
        #define SCATTER1(PV, DF)                                             \
            qv = (unsigned long long)((PV) * FIX_SCALE);                     \
            if ((DF) == 0)        acc_lo += qv;                              \
            else if ((DF) == 128) acc_hi += qv;                              \
            else atomicAdd(a64 + (DF), qv);
        SCATTER1(pv.x, df0)
        SCATTER1(pv.y, df1)
        SCATTER1(pv.z, df2)
        SCATTER1(pv.w, df3)
        #undef SCATTER1
    }
    // exact u64 warp reduction of the two clip buckets
    #pragma unroll
    for (int o = 16; o > 0; o >>= 1) {
        acc_lo += __shfl_xor_sync(FULL, acc_lo, o);
        acc_hi += __shfl_xor_sync(FULL, acc_hi, o);
    }
    if (lane == 0) {
        a64[0]   += acc_lo;
        a64[128] += acc_hi;
    }
    __syncwarp();

    float* avout = g_av + ((size_t)b * LL + i) * AVG;
    #pragma unroll
    for (int c = 0; c < 6; c++) {
        int idx = lane + 32 * c;
        float val = 0.f;
        if (idx < RR)
            val = __ull2float_rn(a64[idx]) * FIX_INV;
        avout[idx] = val;
    }
}

// ===================== K_pv: out = p @ v + av @ emb_v =====================
#define NT2 256

extern "C" __global__ void __launch_bounds__(NT2, 4)
pv_kernel(const float* __restrict__ gp_in, const float* __restrict__ gv,
          const float* __restrict__ gev, float* __restrict__ gout)
{
    __shared__ float ps2[64 * 68];
    __shared__ float vs2[64 * 72];

    const int b    = blockIdx.y;
    const int i0b  = blockIdx.x * 64;
    const int tid  = threadIdx.x;
    const int lane = tid & 31;
    const int warp = tid >> 5;
    const int gid  = lane >> 2;
    const int tid4 = lane & 3;
    const int mrow = (warp & 3) * 16;
    const int ncol = (warp >> 2) * 32;

    const float* psrc = gp_in ? gp_in : g_scores;

    float acc[4][4];
    #pragma unroll
    for (int nt = 0; nt < 4; nt++)
        #pragma unroll
        for (int x = 0; x < 4; x++) acc[nt][x] = 0.f;

    for (int t = 0; t < 19; t++) {
        if (t < 16) {
            const float4* pa = (const float4*)(psrc + ((size_t)b * LL + i0b) * LL + t * 64);
            const float4* va = (const float4*)(gv + ((size_t)b * LL + t * 64) * DD);
            #pragma unroll
            for (int s = 0; s < 4; s++) {
                int f = tid + s * NT2;
                int r = f >> 4, c4 = f & 15;
                *(float4*)(ps2 + r * 68 + c4 * 4) = tf32r4(pa[r * 256 + c4]);
                *(float4*)(vs2 + r * 72 + c4 * 4) = tf32r4(va[f]);
            }
        } else {
            int kc = t - 16;
            const float4* aa = (const float4*)(g_av + ((size_t)b * LL + i0b) * AVG + kc * 64);
            #pragma unroll
            for (int s = 0; s < 4; s++) {
                int f = tid + s * NT2;
                int r = f >> 4, c4 = f & 15;
                *(float4*)(ps2 + r * 68 + c4 * 4) = tf32r4(aa[r * (AVG/4) + c4]);
                int kr = kc * 64 + r;
                float4 ev = make_float4(0.f, 0.f, 0.f, 0.f);
                if (kr < RR)
                    ev = tf32r4(((const float4*)(gev + kr * DD))[c4]);
                *(float4*)(vs2 + r * 72 + c4 * 4) = ev;
            }
        }
        __syncthreads();

        #pragma unroll
        for (int ks = 0; ks < 8; ks++) {
            unsigned a0 = __float_as_uint(ps2[(mrow + gid)     * 68 + ks * 8 + tid4    ]);
            unsigned a1 = __float_as_uint(ps2[(mrow + gid + 8) * 68 + ks * 8 + tid4    ]);
            unsigned a2 = __float_as_uint(ps2[(mrow + gid)     * 68 + ks * 8 + tid4 + 4]);
            unsigned a3 = __float_as_uint(ps2[(mrow + gid + 8) * 68 + ks * 8 + tid4 + 4]);
            #pragma unroll
            for (int nt = 0; nt < 4; nt++) {
                unsigned b0 = __float_as_uint(vs2[(ks * 8 + tid4)     * 72 + ncol + nt * 8 + gid]);
                unsigned b1 = __float_as_uint(vs2[(ks * 8 + tid4 + 4) * 72 + ncol + nt * 8 + gid]);
                MMA_TF32(acc[nt][0], acc[nt][1], acc[nt][2], acc[nt][3],
                         a0, a1, a2, a3, b0, b1);
            }
        }
        __syncthreads();
    }

    #pragma unroll
    for (int nt = 0; nt < 4; nt++) {
        int col = ncol + nt * 8 + tid4 * 2;
        *(float2*)(gout + ((size_t)b * LL + i0b + mrow + gid)     * DD + col) =
            make_float2(acc[nt][0], acc[nt][1]);
        *(float2*)(gout + ((size_t)b * LL + i0b + mrow + gid + 8) * DD + col) =
            make_float2(acc[nt][2], acc[nt][3]);
    }
}

extern "C" void kernel_launch(void* const* d_in, const int* in_sizes, int n_in,
                              void* d_out, int out_size)
{
    const float* q   = (const float*)d_in[0];
    const float* k   = (const float*)d_in[1];
    const float* v   = (const float*)d_in[2];
    const float* w   = (const float*)d_in[3];
    const float* ek  = (const float*)d_in[4];
    const float* ev  = (const float*)d_in[5];
    const int*   pos = (const int*)d_in[6];
    const unsigned char* mask = (const unsigned char*)d_in[7];

    const long OUT_N = (long)BNH * LL * DD;   // 2,097,152
    const long P_N   = (long)BNH * LL * LL;   // 33,554,432

    float* outp = nullptr;
    float* pp   = nullptr;
    if ((long)out_size == OUT_N) {
        outp = (float*)d_out;
    } else if ((long)out_size == P_N) {
        pp = (float*)d_out;
    } else {
        outp = (float*)d_out;
        pp   = (float*)d_out + OUT_N;
    }

    cudaFuncSetAttribute(score_qe_kernel,
                         cudaFuncAttributeMaxDynamicSharedMemorySize, SQ_SMEM);

    dim3 gridSQ(32, BNH);                     // x<16: score tiles, x>=16: qe tiles
    score_qe_kernel<<<gridSQ, 256, SQ_SMEM>>>(q, k, ek);
    dim3 gridS(LL / 8, BNH);                  // (128, 32)
    softmax_kernel<<<gridS, 256>>>(w, pos, mask, pp);
    if (outp) {
        dim3 grid(LL / 64, BNH);              // (16, 32)
        pv_kernel<<<grid, NT2>>>(pp, v, ev, outp);
    }
}

// round 17
// speedup vs baseline: 2.8207x; 1.0364x over previous
#include <cuda_runtime.h>
#include <math.h>

#define BNH 32
#define LL  1024
#define DD  64
#define RR  129
#define AVG 192      // g_av stride (cols 129..191 zero)
#define QEG 136      // g_qe stride

__device__ float g_av[(size_t)BNH * LL * AVG];        // 25 MB
__device__ float g_qe[(size_t)BNH * LL * QEG];        // 17.8 MB
__device__ float g_scores[(size_t)BNH * LL * LL];     // 128 MB raw QK^T (+ p scratch if gp null)

#define FIX_SCALE 4503599627370496.0f   /* 2^52 */
#define FIX_INV   (1.0f / 4503599627370496.0f)

__device__ __forceinline__ unsigned tf32b(float x) {
    unsigned u;
    asm("cvt.rna.tf32.f32 %0, %1;" : "=r"(u) : "f"(x));
    return u;
}
__device__ __forceinline__ float tf32r(float x) { return __uint_as_float(tf32b(x)); }
__device__ __forceinline__ float4 tf32r4(float4 a) {
    a.x = tf32r(a.x); a.y = tf32r(a.y); a.z = tf32r(a.z); a.w = tf32r(a.w);
    return a;
}

#define MMA_TF32(c0,c1,c2,c3,a0,a1,a2,a3,b0,b1)                               \
    asm volatile("mma.sync.aligned.m16n8k8.row.col.f32.tf32.tf32.f32 "        \
                 "{%0,%1,%2,%3}, {%4,%5,%6,%7}, {%8,%9}, {%0,%1,%2,%3};"      \
                 : "+f"(c0), "+f"(c1), "+f"(c2), "+f"(c3)                      \
                 : "r"(a0), "r"(a1), "r"(a2), "r"(a3), "r"(b0), "r"(b1))

// ====== K_score_qe: score GEMM (16 j-tiles) + per-CTA qe tail (reuses q_s) ======
// dynamic smem: q_s 4352 + kbuf 9248 floats = 54400 B  (4 CTAs/SM)
#define SQ_SMEM ((4352 + 9248) * 4)

extern "C" __global__ void __launch_bounds__(256, 4)
score_qe_kernel(const float* __restrict__ gq, const float* __restrict__ gk,
                const float* __restrict__ gek)
{
    extern __shared__ float sm[];
    float* q_s  = sm;             // 64 x 68
    float* kbuf = sm + 4352;      // k tiles 64x68; then emb_k 136x68

    const int b    = blockIdx.y;
    const int i0   = blockIdx.x * 64;
    const int tid  = threadIdx.x;
    const int lane = tid & 31;
    const int warp = tid >> 5;
    const int gid  = lane >> 2;
    const int tid4 = lane & 3;
    const int mrow = (warp & 3) * 16;
    const int ncol = (warp >> 2) * 32;

    {
        const float4* q4 = (const float4*)(gq + ((size_t)b * LL + i0) * DD);
        #pragma unroll
        for (int s = 0; s < 4; s++) {
            int f = tid + s * 256;
            int r = f >> 4, c4 = f & 15;
            *(float4*)(q_s + r * 68 + c4 * 4) = tf32r4(q4[f]);
        }
    }
    __syncthreads();

    // ---------------- score phase: raw scores = Q K^T ----------------
    const size_t row_lo = ((size_t)b * LL + i0 + mrow + gid) * LL;
    const size_t row_hi = row_lo + 8 * LL;

    for (int jt = 0; jt < 16; jt++) {
        {
            const float4* k4 = (const float4*)(gk + ((size_t)b * LL + jt * 64) * DD);
            #pragma unroll
            for (int s = 0; s < 4; s++) {
                int f = tid + s * 256;
                int r = f >> 4, c4 = f & 15;
                *(float4*)(kbuf + r * 68 + c4 * 4) = tf32r4(k4[f]);
            }
        }
        __syncthreads();

        float acc[4][4];
        #pragma unroll
        for (int nt = 0; nt < 4; nt++)
            #pragma unroll
            for (int x = 0; x < 4; x++) acc[nt][x] = 0.f;

        #pragma unroll
        for (int ks = 0; ks < 8; ks++) {
            const float* qa = q_s + (mrow + gid) * 68 + ks * 8 + tid4;
            unsigned a0 = __float_as_uint(qa[0]);
            unsigned a1 = __float_as_uint(qa[8 * 68]);
            unsigned a2 = __float_as_uint(qa[4]);
            unsigned a3 = __float_as_uint(qa[8 * 68 + 4]);
            #pragma unroll
            for (int nt = 0; nt < 4; nt++) {
                const float* kb = kbuf + (ncol + nt * 8 + gid) * 68 + ks * 8 + tid4;
                unsigned b0 = __float_as_uint(kb[0]);
                unsigned b1 = __float_as_uint(kb[4]);
                MMA_TF32(acc[nt][0], acc[nt][1], acc[nt][2], acc[nt][3],
                         a0, a1, a2, a3, b0, b1);
            }
        }

        #pragma unroll
        for (int nt = 0; nt < 4; nt++) {
            int jg = jt * 64 + ncol + nt * 8 + tid4 * 2;
            *(float2*)(g_scores + row_lo + jg) = make_float2(acc[nt][0], acc[nt][1]);
            *(float2*)(g_scores + row_hi + jg) = make_float2(acc[nt][2], acc[nt][3]);
        }
        __syncthreads();
    }

    // ---------------- qe tail: g_qe[i0..i0+63] = q . emb_k^T ----------------
    {
        for (int e = tid; e < 136 * 64; e += 256) {
            int r = e >> 6, d = e & 63;
            kbuf[r * 68 + d] = (r < RR) ? tf32r(gek[r * 64 + d]) : 0.f;
        }
        __syncthreads();

        for (int t = warp; t < 68; t += 8) {
            int mt = t / 17, nt = t % 17;
            float c0 = 0.f, c1 = 0.f, c2 = 0.f, c3 = 0.f;
            #pragma unroll
            for (int ks = 0; ks < 8; ks++) {
                const float* qa = q_s + (mt * 16 + gid) * 68 + ks * 8 + tid4;
                unsigned a0 = __float_as_uint(qa[0]);
                unsigned a1 = __float_as_uint(qa[8 * 68]);
                unsigned a2 = __float_as_uint(qa[4]);
                unsigned a3 = __float_as_uint(qa[8 * 68 + 4]);
                const float* kb = kbuf + (nt * 8 + gid) * 68 + ks * 8 + tid4;
                unsigned b0 = __float_as_uint(kb[0]);
                unsigned b1 = __float_as_uint(kb[4]);
                MMA_TF32(c0, c1, c2, c3, a0, a1, a2, a3, b0, b1);
            }
            int col = nt * 8 + tid4 * 2;
            float* o_lo = g_qe + ((size_t)b * LL + i0 + mt * 16 + gid) * QEG + col;
            *(float2*)o_lo            = make_float2(c0, c1);
            *(float2*)(o_lo + 8*QEG)  = make_float2(c2, c3);
        }
    }
}

// ======== K_softmax: (raw + qe[table] + w)/8, mask -> softmax -> p + av ========
// Clip buckets (df==0 / df==128) accumulate in per-lane u64 registers + exact
// warp shfl reduce; atomics only for interior buckets (exact -> deterministic).
extern "C" __global__ void __launch_bounds__(256, 4)
softmax_kernel(const float* __restrict__ gw, const int* __restrict__ gpos,
               const unsigned char* __restrict__ gmask, float* __restrict__ gp)
{
    __shared__ int posa[LL];
    __shared__ float qe_sm[8][132];
    __shared__ unsigned long long a64s[8 * 132];

    const int b    = blockIdx.y;
    const int i8   = blockIdx.x * 8;
    const int lane = threadIdx.x & 31;
    const int warp = threadIdx.x >> 5;
    const int i    = i8 + warp;                 // row per warp
    const unsigned FULL = 0xffffffffu;

    #pragma unroll
    for (int t = threadIdx.x; t < LL; t += 256) posa[t] = gpos[b * LL + t];
    for (int idx = threadIdx.x; idx < 8 * 33; idx += 256) {
        int r = idx / 33, c4 = idx % 33;
        *(float4*)(&qe_sm[r][c4 * 4]) =
            *(const float4*)(g_qe + ((size_t)b * LL + i8 + r) * QEG + c4 * 4);
    }
    __syncthreads();

    float* pdst = gp ? gp : g_scores;
    const size_t grow = ((size_t)b * LL + i) * LL;
    const float4*  s4 = (const float4*)(g_scores + grow);
    const float4*  w4 = (const float4*)(gw + grow);
    const uchar4*  m4 = (const uchar4*)(gmask + grow);
    const int pi = posa[i];
    const float* qe = qe_sm[warp];

    float4 r4[8];
    float m = -INFINITY;
    #pragma unroll
    for (int c = 0; c < 8; c++) {
        int l4 = lane + 32 * c;
        float4 s = s4[l4];
        float4 w = w4[l4];
        uchar4 mk = m4[l4];
        int4 pj = *(const int4*)(posa + l4 * 4);
        int df0 = max(-64, min(64, pj.x - pi)) + 64;
        int df1 = max(-64, min(64, pj.y - pi)) + 64;
        int df2 = max(-64, min(64, pj.z - pi)) + 64;
        int df3 = max(-64, min(64, pj.w - pi)) + 64;
        s.x = (s.x + qe[df0] + w.x) * 0.125f;
        s.y = (s.y + qe[df1] + w.y) * 0.125f;
        s.z = (s.z + qe[df2] + w.z) * 0.125f;
        s.w = (s.w + qe[df3] + w.w) * 0.125f;
        if (mk.x) s.x = -INFINITY;
        if (mk.y) s.y = -INFINITY;
        if (mk.z) s.z = -INFINITY;
        if (mk.w) s.w = -INFINITY;
        r4[c] = s;
        m = fmaxf(m, fmaxf(fmaxf(s.x, s.y), fmaxf(s.z, s.w)));
    }
    #pragma unroll
    for (int o = 16; o > 0; o >>= 1) m = fmaxf(m, __shfl_xor_sync(FULL, m, o));

    float sum = 0.f;
    #pragma unroll
    for (int c = 0; c < 8; c++) {
        r4[c].x = __expf(r4[c].x - m); sum += r4[c].x;
        r4[c].y = __expf(r4[c].y - m); sum += r4[c].y;
        r4[c].z = __expf(r4[c].z - m); sum += r4[c].z;
        r4[c].w = __expf(r4[c].w - m); sum += r4[c].w;
    }
    #pragma unroll
    for (int o = 16; o > 0; o >>= 1) sum += __shfl_xor_sync(FULL, sum, o);
    float inv = 1.0f / sum;

    unsigned long long* a64 = a64s + (size_t)warp * 132;
    #pragma unroll
    for (int c = 0; c < 5; c++) {
        int idx = lane + 32 * c;
        if (idx < 132) a64[idx] = 0ull;
    }
    __syncwarp();

    unsigned long long acc_lo = 0ull, acc_hi = 0ull;   // df==0 / df==128
    float4* p4 = (float4*)(pdst + grow);
    #pragma unroll
    for (int c = 0; c < 8; c++) {
        int l4 = lane + 32 * c;
        float4 pv;
        pv.x = r4[c].x * inv; pv.y = r4[c].y * inv;
        pv.z = r4[c].z * inv; pv.w = r4[c].w * inv;
        p4[l4] = pv;
        int4 pj = *(const int4*)(posa + l4 * 4);
        int df0 = max(-64, min(64, pj.x - pi)) + 64;
        int df1 = max(-64, min(64, pj.y - pi)) + 64;
        int df2 = max(-64, min(64, pj.z - pi)) + 64;
        int df3 = max(-64, min(64, pj.w - pi)) + 64;
        unsigned long long qv;
        #define SCATTER1(PV, DF)                                             \
            qv = (unsigned long long)((PV) * FIX_SCALE);                     \
            if ((DF) == 0)        acc_lo += qv;                              \
            else if ((DF) == 128) acc_hi += qv;                              \
            else atomicAdd(a64 + (DF), qv);
        SCATTER1(pv.x, df0)
        SCATTER1(pv.y, df1)
        SCATTER1(pv.z, df2)
        SCATTER1(pv.w, df3)
        #undef SCATTER1
    }
    #pragma unroll
    for (int o = 16; o > 0; o >>= 1) {
        acc_lo += __shfl_xor_sync(FULL, acc_lo, o);
        acc_hi += __shfl_xor_sync(FULL, acc_hi, o);
    }
    if (lane == 0) {
        a64[0]   += acc_lo;
        a64[128] += acc_hi;
    }
    __syncwarp();

    float* avout = g_av + ((size_t)b * LL + i) * AVG;
    #pragma unroll
    for (int c = 0; c < 6; c++) {
        int idx = lane + 32 * c;
        float val = 0.f;
        if (idx < RR)
            val = __ull2float_rn(a64[idx]) * FIX_INV;
        avout[idx] = val;
    }
}

// ===================== K_pv: out = p @ v + av @ emb_v =====================
#define NT2 256

extern "C" __global__ void __launch_bounds__(NT2, 4)
pv_kernel(const float* __restrict__ gp_in, const float* __restrict__ gv,
          const float* __restrict__ gev, float* __restrict__ gout)
{
    __shared__ float ps2[64 * 68];
    __shared__ float vs2[64 * 72];

    const int b    = blockIdx.y;
    const int i0b  = blockIdx.x * 64;
    const int tid  = threadIdx.x;
    const int lane = tid & 31;
    const int warp = tid >> 5;
    const int gid  = lane >> 2;
    const int tid4 = lane & 3;
    const int mrow = (warp & 3) * 16;
    const int ncol = (warp >> 2) * 32;

    const float* psrc = gp_in ? gp_in : g_scores;

    float acc[4][4];
    #pragma unroll
    for (int nt = 0; nt < 4; nt++)
        #pragma unroll
        for (int x = 0; x < 4; x++) acc[nt][x] = 0.f;

    for (int t = 0; t < 19; t++) {
        if (t < 16) {
            const float4* pa = (const float4*)(psrc + ((size_t)b * LL + i0b) * LL + t * 64);
            const float4* va = (const float4*)(gv + ((size_t)b * LL + t * 64) * DD);
            #pragma unroll
            for (int s = 0; s < 4; s++) {
                int f = tid + s * NT2;
                int r = f >> 4, c4 = f & 15;
                *(float4*)(ps2 + r * 68 + c4 * 4) = tf32r4(pa[r * 256 + c4]);
                *(float4*)(vs2 + r * 72 + c4 * 4) = tf32r4(va[f]);
            }
        } else {
            int kc = t - 16;
            const float4* aa = (const float4*)(g_av + ((size_t)b * LL + i0b) * AVG + kc * 64);
            #pragma unroll
            for (int s = 0; s < 4; s++) {
                int f = tid + s * NT2;
                int r = f >> 4, c4 = f & 15;
                *(float4*)(ps2 + r * 68 + c4 * 4) = tf32r4(aa[r * (AVG/4) + c4]);
                int kr = kc * 64 + r;
                float4 ev = make_float4(0.f, 0.f, 0.f, 0.f);
                if (kr < RR)
                    ev = tf32r4(((const float4*)(gev + kr * DD))[c4]);
                *(float4*)(vs2 + r * 72 + c4 * 4) = ev;
            }
        }
        __syncthreads();

        #pragma unroll
        for (int ks = 0; ks < 8; ks++) {
            unsigned a0 = __float_as_uint(ps2[(mrow + gid)     * 68 + ks * 8 + tid4    ]);
            unsigned a1 = __float_as_uint(ps2[(mrow + gid + 8) * 68 + ks * 8 + tid4    ]);
            unsigned a2 = __float_as_uint(ps2[(mrow + gid)     * 68 + ks * 8 + tid4 + 4]);
            unsigned a3 = __float_as_uint(ps2[(mrow + gid + 8) * 68 + ks * 8 + tid4 + 4]);
            #pragma unroll
            for (int nt = 0; nt < 4; nt++) {
                unsigned b0 = __float_as_uint(vs2[(ks * 8 + tid4)     * 72 + ncol + nt * 8 + gid]);
                unsigned b1 = __float_as_uint(vs2[(ks * 8 + tid4 + 4) * 72 + ncol + nt * 8 + gid]);
                MMA_TF32(acc[nt][0], acc[nt][1], acc[nt][2], acc[nt][3],
                         a0, a1, a2, a3, b0, b1);
            }
        }
        __syncthreads();
    }

    #pragma unroll
    for (int nt = 0; nt < 4; nt++) {
        int col = ncol + nt * 8 + tid4 * 2;
        *(float2*)(gout + ((size_t)b * LL + i0b + mrow + gid)     * DD + col) =
            make_float2(acc[nt][0], acc[nt][1]);
        *(float2*)(gout + ((size_t)b * LL + i0b + mrow + gid + 8) * DD + col) =
            make_float2(acc[nt][2], acc[nt][3]);
    }
}

extern "C" void kernel_launch(void* const* d_in, const int* in_sizes, int n_in,
                              void* d_out, int out_size)
{
    const float* q   = (const float*)d_in[0];
    const float* k   = (const float*)d_in[1];
    const float* v   = (const float*)d_in[2];
    const float* w   = (const float*)d_in[3];
    const float* ek  = (const float*)d_in[4];
    const float* ev  = (const float*)d_in[5];
    const int*   pos = (const int*)d_in[6];
    const unsigned char* mask = (const unsigned char*)d_in[7];

    const long OUT_N = (long)BNH * LL * DD;   // 2,097,152
    const long P_N   = (long)BNH * LL * LL;   // 33,554,432

    float* outp = nullptr;
    float* pp   = nullptr;
    if ((long)out_size == OUT_N) {
        outp = (float*)d_out;
    } else if ((long)out_size == P_N) {
        pp = (float*)d_out;
    } else {
        outp = (float*)d_out;
        pp   = (float*)d_out + OUT_N;
    }

    cudaFuncSetAttribute(score_qe_kernel,
                         cudaFuncAttributeMaxDynamicSharedMemorySize, SQ_SMEM);

    dim3 grid(LL / 64, BNH);                  // (16, 32)
    score_qe_kernel<<<grid, 256, SQ_SMEM>>>(q, k, ek);
    dim3 gridS(LL / 8, BNH);                  // (128, 32)
    softmax_kernel<<<gridS, 256>>>(w, pos, mask, pp);
    if (outp)
        pv_kernel<<<grid, NT2>>>(pp, v, ev, outp);
}